// round 9
// baseline (speedup 1.0000x reference)
#include <cuda_runtime.h>
#include <cuda_bf16.h>
#include <cstdint>

#define N_NODES 50000
#define N_EDGES 300000
#define D 256
#define F_IN 11
#define M_TILES 391
#define M_PAD (M_TILES * 128)

// ---------------- static scratch ------------------------------------------------
__device__ __align__(16) __nv_bfloat16 g_a0[(size_t)M_PAD * D];  // A hi split
__device__ __align__(16) __nv_bfloat16 g_a1[(size_t)M_PAD * D];  // A lo split
__device__ __align__(16) float g_b[(size_t)N_NODES * D];         // GEMM output fp32
__device__ __align__(16) __nv_bfloat16 g_ws[2][2][D * D];        // W splits [layer][split][n*256+k]
__device__ float g_dis[N_NODES];
__device__ int   g_cnt[N_NODES];
__device__ int   g_rowptr[N_NODES + 1];
__device__ int   g_cursor[N_NODES];
__device__ int   g_col[N_EDGES];
__device__ int   g_part[64];
__device__ int   g_poff[64];

// ---------------- helpers -------------------------------------------------------
__device__ __forceinline__ uint32_t smem_u32(const void* p) {
    uint32_t a;
    asm("{ .reg .u64 t; cvta.to.shared.u64 t, %1; cvt.u32.u64 %0, t; }" : "=r"(a) : "l"(p));
    return a;
}
__device__ __forceinline__ void cpa16(uint32_t d, const void* s) {
    asm volatile("cp.async.cg.shared.global [%0], [%1], 16;" :: "r"(d), "l"(s));
}
__device__ __forceinline__ void ldsm4(uint32_t* r, uint32_t a) {
    asm volatile("ldmatrix.sync.aligned.m8n8.x4.shared.b16 {%0,%1,%2,%3}, [%4];"
                 : "=r"(r[0]), "=r"(r[1]), "=r"(r[2]), "=r"(r[3]) : "r"(a));
}
__device__ __forceinline__ void mma16(float* c, const uint32_t* a, const uint32_t* b) {
    asm volatile("mma.sync.aligned.m16n8k16.row.col.f32.bf16.bf16.f32 "
                 "{%0,%1,%2,%3},{%4,%5,%6,%7},{%8,%9},{%0,%1,%2,%3};"
                 : "+f"(c[0]), "+f"(c[1]), "+f"(c[2]), "+f"(c[3])
                 : "r"(a[0]), "r"(a[1]), "r"(a[2]), "r"(a[3]), "r"(b[0]), "r"(b[1]));
}
__device__ __forceinline__ void split2(float x, __nv_bfloat16& s0, __nv_bfloat16& s1) {
    s0 = __float2bfloat16(x);
    s1 = __float2bfloat16(x - __bfloat162float(s0));
}

// ---------------- prep: weight split --------------------------------------------
__global__ void k_prep(const float* __restrict__ W1, const float* __restrict__ W2) {
    int i = blockIdx.x * 256 + threadIdx.x;   // i = k*256+n
    int k = i >> 8, n = i & 255;
    __nv_bfloat16 s0, s1;
    split2(W1[i], s0, s1);
    g_ws[0][0][n * 256 + k] = s0; g_ws[0][1][n * 256 + k] = s1;
    split2(W2[i], s0, s1);
    g_ws[1][0][n * 256 + k] = s0; g_ws[1][1][n * 256 + k] = s1;
}

// ---------------- CSR build -----------------------------------------------------
// g_cnt starts zero (static init on first call; re-zeroed by k_scan_c each call)
__global__ void k_count(const int* __restrict__ ei) {
    int e = blockIdx.x * blockDim.x + threadIdx.x;
    if (e < N_EDGES) atomicAdd(&g_cnt[ei[N_EDGES + e]], 1);
}

#define SCAN_BLKS 49
__global__ __launch_bounds__(1024) void k_scan_a() {
    __shared__ int s[1024];
    int t = threadIdx.x, i = blockIdx.x * 1024 + t;
    int v = (i < N_NODES) ? g_cnt[i] : 0;
    s[t] = v;
    __syncthreads();
    #pragma unroll
    for (int off = 1; off < 1024; off <<= 1) {
        int tmp = (t >= off) ? s[t - off] : 0;
        __syncthreads();
        s[t] += tmp;
        __syncthreads();
    }
    if (i < N_NODES) g_rowptr[i] = s[t] - v;   // block-local exclusive
    if (t == 1023) g_part[blockIdx.x] = s[t];
}
__global__ void k_scan_b() {
    __shared__ int s[64];
    int t = threadIdx.x;
    int v = (t < SCAN_BLKS) ? g_part[t] : 0;
    s[t] = v;
    __syncthreads();
    #pragma unroll
    for (int off = 1; off < 64; off <<= 1) {
        int tmp = (t >= off) ? s[t - off] : 0;
        __syncthreads();
        s[t] += tmp;
        __syncthreads();
    }
    if (t < SCAN_BLKS) g_poff[t] = s[t] - v;
}
__global__ __launch_bounds__(1024) void k_scan_c() {
    int t = threadIdx.x, i = blockIdx.x * 1024 + t;
    if (i < N_NODES) {
        int r = g_rowptr[i] + g_poff[blockIdx.x];
        g_rowptr[i] = r;
        g_cursor[i] = r;
        g_dis[i] = rsqrtf((float)(g_cnt[i] + 1));
        g_cnt[i] = 0;                    // restore for next call (graph replay)
    }
    if (i == N_NODES) g_rowptr[N_NODES] = N_EDGES;
}
__global__ void k_fill(const int* __restrict__ ei) {
    int e = blockIdx.x * blockDim.x + threadIdx.x;
    if (e < N_EDGES) {
        int d = ei[N_EDGES + e];
        int p = atomicAdd(&g_cursor[d], 1);
        g_col[p] = ei[e];
    }
}

// ---------------- embed: g_a0/g_a1 = split2(relu(x @ W_embed + b)), pad zeros ---
#define EMB_NODES 8
__global__ __launch_bounds__(256) void k_embed(const float* __restrict__ x,
                                               const float* __restrict__ W,
                                               const float* __restrict__ b) {
    __shared__ float Ws[F_IN * D];
    __shared__ float xs[EMB_NODES * F_IN];
    int t = threadIdx.x;
    for (int i = t; i < F_IN * D; i += 256) Ws[i] = W[i];
    int n0 = blockIdx.x * EMB_NODES;
    for (int i = t; i < EMB_NODES * F_IN; i += 256) {
        int node = n0 + i / F_IN;
        xs[i] = (node < N_NODES) ? x[(size_t)node * F_IN + (i % F_IN)] : 0.0f;
    }
    __syncthreads();
    float bv = b[t];
    #pragma unroll 1
    for (int j = 0; j < EMB_NODES; j++) {
        int node = n0 + j;
        if (node >= M_PAD) break;
        __nv_bfloat16 s0 = __float2bfloat16(0.0f), s1 = s0;
        if (node < N_NODES) {
            float acc = bv;
            #pragma unroll
            for (int k = 0; k < F_IN; k++) acc += xs[j * F_IN + k] * Ws[k * D + t];
            split2(fmaxf(acc, 0.0f), s0, s1);
        }
        size_t idx = (size_t)node * D + t;
        g_a0[idx] = s0;
        g_a1[idx] = s1;
    }
}

// ---------------- bf16x2 mma.sync GEMM, 2 CTAs/SM, deep cp.async pipeline -------
// grid 296 persistent CTAs: nq = cta&3 (N quarter, 64 cols), m-tiles stride 74.
// smem 112KB: B resident [2 spl][64 n][256 k] = 64KB at 0;
//             A ring: 6 bufs x [128 m][64B row: hi k16 32B | lo k16 32B] = 48KB.
#define SMEM_A_OFF 65536
#define A_BUFS 6
#define SMEM_GEMM (SMEM_A_OFF + A_BUFS * 8192)   // 114688

__device__ __forceinline__ void load_achunk16(uint32_t sb, int t, int m0, int c) {
    int k0 = c * 16;
    uint32_t ab = sb + SMEM_A_OFF + (c % A_BUFS) * 8192;
    #pragma unroll
    for (int j = 0; j < 2; j++) {
        int g = t + 256 * j;                  // 0..511 16B units
        int row = g >> 2, u = g & 3;          // u: 0,1 = hi k0/k8 ; 2,3 = lo k0/k8
        uint32_t dst = ab + row * 64 + ((u ^ ((row >> 1) & 3)) << 4);
        const __nv_bfloat16* base = (u < 2) ? g_a0 : g_a1;
        cpa16(dst, base + (size_t)(m0 + row) * D + k0 + (u & 1) * 8);
    }
    asm volatile("cp.async.commit_group;" ::: "memory");
}

__global__ __launch_bounds__(256, 2) void k_gemm_bf16(const __nv_bfloat16* __restrict__ Wb,
                                                      float* __restrict__ out) {
    extern __shared__ __align__(1024) char smem[];
    const uint32_t sb = smem_u32(smem);
    const int t = threadIdx.x, wid = t >> 5, lane = t & 31;
    const int nq = blockIdx.x & 3;
    const int wm = wid & 3, wn = wid >> 2;
    const int dq = lane >> 3, Lr = lane & 7;

    // load resident B (quarter of W, both splits), one commit group (group 0)
    #pragma unroll
    for (int j = 0; j < 16; j++) {
        int u = t + 256 * j;                  // 0..4095 16B units
        int s = u >> 11;
        int row = (u & 2047) >> 5;
        int q = u & 31;
        uint32_t dst = sb + s * 32768 + row * 512 + ((q ^ (row & 7)) << 4);
        cpa16(dst, Wb + s * (D * D) + (size_t)(nq * 64 + row) * D + q * 8);
    }
    asm volatile("cp.async.commit_group;" ::: "memory");

    // lane geometry
    int rowA[2], swzA[2];
    #pragma unroll
    for (int it = 0; it < 2; it++) {
        rowA[it] = wm * 32 + it * 16 + Lr + (dq & 1) * 8;
        swzA[it] = (rowA[it] >> 1) & 3;
    }
    const int uhiA = dq >> 1;                 // k8-half select
    int rowB[2], xorB[2];
    #pragma unroll
    for (int g4 = 0; g4 < 2; g4++) {
        rowB[g4] = wn * 32 + g4 * 16 + (dq >> 1) * 8 + Lr;
        xorB[g4] = rowB[g4] & 7;
    }
    const int qloB = dq & 1;

    #pragma unroll 1
    for (int mt = blockIdx.x >> 2; mt < M_TILES; mt += 74) {
        int m0 = mt * 128;
        float C[2][4][4];
        #pragma unroll
        for (int it = 0; it < 2; it++)
            #pragma unroll
            for (int f = 0; f < 4; f++)
                #pragma unroll
                for (int q = 0; q < 4; q++) C[it][f][q] = 0.0f;

        __syncthreads();                      // all warps done reading A ring of prev tile
        #pragma unroll
        for (int j = 0; j < 5; j++) load_achunk16(sb, t, m0, j);

        #pragma unroll 1
        for (int c = 0; c < 16; c++) {
            // chunk c's group must be complete
            if (c < 12)      asm volatile("cp.async.wait_group 4;" ::: "memory");
            else if (c == 12) asm volatile("cp.async.wait_group 3;" ::: "memory");
            else if (c == 13) asm volatile("cp.async.wait_group 2;" ::: "memory");
            else if (c == 14) asm volatile("cp.async.wait_group 1;" ::: "memory");
            else              asm volatile("cp.async.wait_group 0;" ::: "memory");
            __syncthreads();

            uint32_t Ab = sb + SMEM_A_OFF + (c % A_BUFS) * 8192;
            uint32_t ah[2][4], al[2][4];
            #pragma unroll
            for (int it = 0; it < 2; it++) {
                uint32_t base = Ab + rowA[it] * 64;
                ldsm4(ah[it], base + ((uhiA ^ swzA[it]) << 4));
                ldsm4(al[it], base + (((2 + uhiA) ^ swzA[it]) << 4));
            }
            uint32_t bh[4][2], bl[4][2];
            #pragma unroll
            for (int g4 = 0; g4 < 2; g4++) {
                int qb = c * 2 + qloB;
                uint32_t base = sb + rowB[g4] * 512 + ((qb ^ xorB[g4]) << 4);
                uint32_t r[4];
                ldsm4(r, base);
                bh[2 * g4][0] = r[0]; bh[2 * g4][1] = r[1];
                bh[2 * g4 + 1][0] = r[2]; bh[2 * g4 + 1][1] = r[3];
                ldsm4(r, base + 32768);
                bl[2 * g4][0] = r[0]; bl[2 * g4][1] = r[1];
                bl[2 * g4 + 1][0] = r[2]; bl[2 * g4 + 1][1] = r[3];
            }
            #pragma unroll
            for (int it = 0; it < 2; it++)
                #pragma unroll
                for (int f = 0; f < 4; f++) {
                    mma16(C[it][f], ah[it], bh[f]);
                    mma16(C[it][f], ah[it], bl[f]);
                    mma16(C[it][f], al[it], bh[f]);
                }

            if (c + 5 < 16) load_achunk16(sb, t, m0, c + 5);
        }

        // epilogue: direct gmem stores
        #pragma unroll
        for (int it = 0; it < 2; it++) {
            int m = m0 + wm * 32 + it * 16 + (lane >> 2);
            #pragma unroll
            for (int f = 0; f < 4; f++) {
                int col = nq * 64 + wn * 32 + f * 8 + (lane & 3) * 2;
                if (m < N_NODES)
                    *(float2*)(out + (size_t)m * D + col) = make_float2(C[it][f][0], C[it][f][1]);
                if (m + 8 < N_NODES)
                    *(float2*)(out + (size_t)(m + 8) * D + col) = make_float2(C[it][f][2], C[it][f][3]);
            }
        }
    }
}

// ---------------- aggregation: gather over CSR ----------------------------------
// out[i] = bias + dis[i]^2 * hw[i] + sum_{e: dst=i} dis[i]*dis[src] * hw[src]
template<bool RELU, bool TO_SPLITS>
__global__ __launch_bounds__(256) void k_agg(const float* __restrict__ bias,
                                             float* __restrict__ out_ext) {
    int gw = (blockIdx.x * 256 + threadIdx.x) >> 5;
    int lane = threadIdx.x & 31;
    if (gw >= N_NODES) return;
    const float* hw = g_b;
    float dd = g_dis[gw];
    int c0 = lane * 8;
    const float4* hp = (const float4*)(hw + (size_t)gw * D + c0);
    float4 h0 = hp[0], h1 = hp[1];
    float4 bb0 = *(const float4*)(bias + c0);
    float4 bb1 = *(const float4*)(bias + c0 + 4);
    float sw = dd * dd;
    float v[8];
    v[0] = bb0.x + h0.x * sw; v[1] = bb0.y + h0.y * sw;
    v[2] = bb0.z + h0.z * sw; v[3] = bb0.w + h0.w * sw;
    v[4] = bb1.x + h1.x * sw; v[5] = bb1.y + h1.y * sw;
    v[6] = bb1.z + h1.z * sw; v[7] = bb1.w + h1.w * sw;
    int e = g_rowptr[gw], e1 = g_rowptr[gw + 1];
    for (; e + 1 < e1; e += 2) {
        int s0 = g_col[e], s1 = g_col[e + 1];
        float w0 = dd * g_dis[s0], w1 = dd * g_dis[s1];
        const float4* p0 = (const float4*)(hw + (size_t)s0 * D + c0);
        const float4* p1 = (const float4*)(hw + (size_t)s1 * D + c0);
        float4 x0 = p0[0], x1 = p0[1];
        float4 y0 = p1[0], y1 = p1[1];
        v[0] += x0.x * w0 + y0.x * w1; v[1] += x0.y * w0 + y0.y * w1;
        v[2] += x0.z * w0 + y0.z * w1; v[3] += x0.w * w0 + y0.w * w1;
        v[4] += x1.x * w0 + y1.x * w1; v[5] += x1.y * w0 + y1.y * w1;
        v[6] += x1.z * w0 + y1.z * w1; v[7] += x1.w * w0 + y1.w * w1;
    }
    if (e < e1) {
        int s0 = g_col[e];
        float w0 = dd * g_dis[s0];
        const float4* p0 = (const float4*)(hw + (size_t)s0 * D + c0);
        float4 x0 = p0[0], x1 = p0[1];
        v[0] += x0.x * w0; v[1] += x0.y * w0; v[2] += x0.z * w0; v[3] += x0.w * w0;
        v[4] += x1.x * w0; v[5] += x1.y * w0; v[6] += x1.z * w0; v[7] += x1.w * w0;
    }
    if (RELU) {
        #pragma unroll
        for (int i = 0; i < 8; i++) v[i] = fmaxf(v[i], 0.0f);
    }
    if (TO_SPLITS) {
        __align__(16) __nv_bfloat16 s0[8], s1[8];
        #pragma unroll
        for (int i = 0; i < 8; i++) split2(v[i], s0[i], s1[i]);
        size_t idx = (size_t)gw * D + c0;
        *(uint4*)&g_a0[idx] = *(const uint4*)s0;
        *(uint4*)&g_a1[idx] = *(const uint4*)s1;
    } else {
        float4* op = (float4*)(out_ext + (size_t)gw * D + c0);
        op[0] = make_float4(v[0], v[1], v[2], v[3]);
        op[1] = make_float4(v[4], v[5], v[6], v[7]);
    }
}

// ---------------- launch --------------------------------------------------------
extern "C" void kernel_launch(void* const* d_in, const int* in_sizes, int n_in,
                              void* d_out, int out_size) {
    const float* x       = (const float*)d_in[0];
    const int*   ei      = (const int*)d_in[1];
    const float* W_embed = (const float*)d_in[2];
    const float* b_embed = (const float*)d_in[3];
    const float* W1      = (const float*)d_in[4];
    const float* b1      = (const float*)d_in[5];
    const float* W2      = (const float*)d_in[6];
    const float* b2      = (const float*)d_in[7];
    float* out = (float*)d_out;

    cudaFuncSetAttribute(k_gemm_bf16, cudaFuncAttributeMaxDynamicSharedMemorySize, SMEM_GEMM);

    __nv_bfloat16* ws = nullptr;
    float* gb = nullptr;
    cudaGetSymbolAddress((void**)&ws, g_ws);
    cudaGetSymbolAddress((void**)&gb, g_b);

    int agg_blocks = (N_NODES * 32 + 255) / 256;

    // slots 1-3: prep (gemm lands at slot 4 = ncu capture slot)
    k_prep<<<(D * D) / 256, 256>>>(W1, W2);
    k_count<<<(N_EDGES + 255) / 256, 256>>>(ei);
    k_embed<<<(M_PAD + EMB_NODES - 1) / EMB_NODES, 256>>>(x, W_embed, b_embed);

    // layer 1 GEMM (slot 4)
    k_gemm_bf16<<<296, 256, SMEM_GEMM>>>(ws, gb);

    // CSR finish (independent of GEMM)
    k_scan_a<<<SCAN_BLKS, 1024>>>();
    k_scan_b<<<1, 64>>>();
    k_scan_c<<<SCAN_BLKS, 1024>>>();
    k_fill<<<(N_EDGES + 255) / 256, 256>>>(ei);

    // layer 1 aggregation -> splits for layer 2
    k_agg<true, true><<<agg_blocks, 256>>>(b1, nullptr);

    // layer 2
    k_gemm_bf16<<<296, 256, SMEM_GEMM>>>(ws + 2 * D * D, gb);
    k_agg<false, false><<<agg_blocks, 256>>>(b2, out);
}

// round 10
// speedup vs baseline: 1.5736x; 1.5736x over previous
#include <cuda_runtime.h>
#include <cuda_bf16.h>
#include <cstdint>

#define N_NODES 50000
#define N_EDGES 300000
#define D 256
#define F_IN 11
#define M_TILES 391
#define M_PAD (M_TILES * 128)

// ---------------- static scratch ------------------------------------------------
__device__ __align__(16) __nv_bfloat16 g_a0[(size_t)M_PAD * D];  // A hi split
__device__ __align__(16) __nv_bfloat16 g_a1[(size_t)M_PAD * D];  // A lo split
__device__ __align__(16) float g_b[(size_t)N_NODES * D];         // GEMM output fp32
__device__ __align__(16) __nv_bfloat16 g_ws[2][2][D * D];        // W splits [layer][split][n*256+k]
__device__ float g_dis[N_NODES];
__device__ int   g_cnt[N_NODES];
__device__ int   g_rowptr[N_NODES + 1];
__device__ int   g_cursor[N_NODES];
__device__ int   g_col[N_EDGES];
__device__ int   g_part[64];

// ---------------- helpers -------------------------------------------------------
__device__ __forceinline__ uint32_t smem_u32(const void* p) {
    uint32_t a;
    asm("{ .reg .u64 t; cvta.to.shared.u64 t, %1; cvt.u32.u64 %0, t; }" : "=r"(a) : "l"(p));
    return a;
}
__device__ __forceinline__ void cpa16(uint32_t d, const void* s) {
    asm volatile("cp.async.cg.shared.global [%0], [%1], 16;" :: "r"(d), "l"(s));
}
__device__ __forceinline__ void ldsm4(uint32_t* r, uint32_t a) {
    asm volatile("ldmatrix.sync.aligned.m8n8.x4.shared.b16 {%0,%1,%2,%3}, [%4];"
                 : "=r"(r[0]), "=r"(r[1]), "=r"(r[2]), "=r"(r[3]) : "r"(a));
}
__device__ __forceinline__ void mma16(float* c, const uint32_t* a, const uint32_t* b) {
    asm volatile("mma.sync.aligned.m16n8k16.row.col.f32.bf16.bf16.f32 "
                 "{%0,%1,%2,%3},{%4,%5,%6,%7},{%8,%9},{%0,%1,%2,%3};"
                 : "+f"(c[0]), "+f"(c[1]), "+f"(c[2]), "+f"(c[3])
                 : "r"(a[0]), "r"(a[1]), "r"(a[2]), "r"(a[3]), "r"(b[0]), "r"(b[1]));
}
__device__ __forceinline__ void split2(float x, __nv_bfloat16& s0, __nv_bfloat16& s1) {
    s0 = __float2bfloat16(x);
    s1 = __float2bfloat16(x - __bfloat162float(s0));
}

// ---------------- prep: weight split --------------------------------------------
__global__ void k_prep(const float* __restrict__ W1, const float* __restrict__ W2) {
    int i = blockIdx.x * 256 + threadIdx.x;   // i = k*256+n
    int k = i >> 8, n = i & 255;
    __nv_bfloat16 s0, s1;
    split2(W1[i], s0, s1);
    g_ws[0][0][n * 256 + k] = s0; g_ws[0][1][n * 256 + k] = s1;
    split2(W2[i], s0, s1);
    g_ws[1][0][n * 256 + k] = s0; g_ws[1][1][n * 256 + k] = s1;
}

// ---------------- CSR build -----------------------------------------------------
// g_cnt starts zero (static init on first call; re-zeroed by k_scan_c each call)
__global__ void k_count4(const int* __restrict__ ei) {
    int i = blockIdx.x * 256 + threadIdx.x;
    if (i < N_EDGES / 4) {
        int4 d = ((const int4*)(ei + N_EDGES))[i];
        atomicAdd(&g_cnt[d.x], 1);
        atomicAdd(&g_cnt[d.y], 1);
        atomicAdd(&g_cnt[d.z], 1);
        atomicAdd(&g_cnt[d.w], 1);
    }
}

#define SCAN_BLKS 49
__global__ __launch_bounds__(1024) void k_scan_a() {
    __shared__ int s[1024];
    int t = threadIdx.x, i = blockIdx.x * 1024 + t;
    int v = (i < N_NODES) ? g_cnt[i] : 0;
    s[t] = v;
    __syncthreads();
    #pragma unroll
    for (int off = 1; off < 1024; off <<= 1) {
        int tmp = (t >= off) ? s[t - off] : 0;
        __syncthreads();
        s[t] += tmp;
        __syncthreads();
    }
    if (i < N_NODES) g_rowptr[i] = s[t] - v;   // block-local exclusive
    if (t == 1023) g_part[blockIdx.x] = s[t];
}
__global__ __launch_bounds__(1024) void k_scan_c() {
    __shared__ int soff;
    int t = threadIdx.x, bid = blockIdx.x, i = bid * 1024 + t;
    if (t == 0) {
        int s = 0;
        for (int j = 0; j < bid; j++) s += g_part[j];
        soff = s;
    }
    __syncthreads();
    int off = soff;
    if (i < N_NODES) {
        int r = g_rowptr[i] + off;
        g_rowptr[i] = r;
        g_cursor[i] = r;
        g_dis[i] = rsqrtf((float)(g_cnt[i] + 1));
        g_cnt[i] = 0;                    // restore for next call (graph replay)
    }
    if (i == N_NODES) g_rowptr[N_NODES] = N_EDGES;
}
__global__ void k_fill4(const int* __restrict__ ei) {
    int i = blockIdx.x * 256 + threadIdx.x;
    if (i < N_EDGES / 4) {
        int4 s = ((const int4*)ei)[i];
        int4 d = ((const int4*)(ei + N_EDGES))[i];
        int p;
        p = atomicAdd(&g_cursor[d.x], 1); g_col[p] = s.x;
        p = atomicAdd(&g_cursor[d.y], 1); g_col[p] = s.y;
        p = atomicAdd(&g_cursor[d.z], 1); g_col[p] = s.z;
        p = atomicAdd(&g_cursor[d.w], 1); g_col[p] = s.w;
    }
}

// ---------------- embed: g_a0/g_a1 = split2(relu(x @ W_embed + b)), pad zeros ---
#define EMB_NODES 8
__global__ __launch_bounds__(256) void k_embed(const float* __restrict__ x,
                                               const float* __restrict__ W,
                                               const float* __restrict__ b) {
    __shared__ float Ws[F_IN * D];
    __shared__ float xs[EMB_NODES * F_IN];
    int t = threadIdx.x;
    for (int i = t; i < F_IN * D; i += 256) Ws[i] = W[i];
    int n0 = blockIdx.x * EMB_NODES;
    for (int i = t; i < EMB_NODES * F_IN; i += 256) {
        int node = n0 + i / F_IN;
        xs[i] = (node < N_NODES) ? x[(size_t)node * F_IN + (i % F_IN)] : 0.0f;
    }
    __syncthreads();
    float bv = b[t];
    #pragma unroll 1
    for (int j = 0; j < EMB_NODES; j++) {
        int node = n0 + j;
        if (node >= M_PAD) break;
        __nv_bfloat16 s0 = __float2bfloat16(0.0f), s1 = s0;
        if (node < N_NODES) {
            float acc = bv;
            #pragma unroll
            for (int k = 0; k < F_IN; k++) acc += xs[j * F_IN + k] * Ws[k * D + t];
            split2(fmaxf(acc, 0.0f), s0, s1);
        }
        size_t idx = (size_t)node * D + t;
        g_a0[idx] = s0;
        g_a1[idx] = s1;
    }
}

// ---------------- bf16x2 mma.sync GEMM, 2 CTAs/SM, 3-deep A ring ----------------
// grid 296 persistent CTAs: nq = cta&3 (N quarter, 64 cols), m-tiles stride 74.
// smem 112KB: B resident [2 spl][64 n][256 k] = 64KB at 0;
//             A ring: 3 bufs x [128 m][128B row: hi k32 64B | lo k32 64B] = 48KB.
#define SMEM_A_OFF 65536
#define A_BUFS 3
#define SMEM_GEMM (SMEM_A_OFF + A_BUFS * 16384)   // 114688

__device__ __forceinline__ void load_achunk(uint32_t sb, int t, int m0, int c) {
    int k0 = c * 32;
    uint32_t ab = sb + SMEM_A_OFF + (c % A_BUFS) * 16384;
    #pragma unroll
    for (int j = 0; j < 4; j++) {
        int u = t + 256 * j;                  // 0..1023 16B units
        int row = u >> 3, uu = u & 7;         // uu<4: hi, else lo
        uint32_t dst = ab + row * 128 + ((uu ^ (row & 7)) << 4);
        const __nv_bfloat16* base = (uu < 4) ? g_a0 : g_a1;
        cpa16(dst, base + (size_t)(m0 + row) * D + k0 + (uu & 3) * 8);
    }
    asm volatile("cp.async.commit_group;" ::: "memory");
}

__global__ __launch_bounds__(256, 2) void k_gemm_bf16(const __nv_bfloat16* __restrict__ Wb,
                                                      float* __restrict__ out) {
    extern __shared__ __align__(1024) char smem[];
    const uint32_t sb = smem_u32(smem);
    const int t = threadIdx.x, wid = t >> 5, lane = t & 31;
    const int nq = blockIdx.x & 3;
    const int wm = wid & 3, wn = wid >> 2;
    const int dq = lane >> 3, Lr = lane & 7;

    // load resident B (quarter of W, both splits), one commit group
    #pragma unroll
    for (int j = 0; j < 16; j++) {
        int u = t + 256 * j;                  // 0..4095 16B units
        int s = u >> 11;
        int row = (u & 2047) >> 5;
        int q = u & 31;
        uint32_t dst = sb + s * 32768 + row * 512 + ((q ^ (row & 7)) << 4);
        cpa16(dst, Wb + s * (D * D) + (size_t)(nq * 64 + row) * D + q * 8);
    }
    asm volatile("cp.async.commit_group;" ::: "memory");

    // lane geometry
    int rowA[2], xorA[2];
    #pragma unroll
    for (int it = 0; it < 2; it++) {
        rowA[it] = wm * 32 + it * 16 + Lr + (dq & 1) * 8;
        xorA[it] = rowA[it] & 7;
    }
    const int uhiA = dq >> 1;
    int rowB[2], xorB[2];
    #pragma unroll
    for (int g4 = 0; g4 < 2; g4++) {
        rowB[g4] = wn * 32 + g4 * 16 + (dq >> 1) * 8 + Lr;
        xorB[g4] = rowB[g4] & 7;
    }
    const int qloB = dq & 1;

    #pragma unroll 1
    for (int mt = blockIdx.x >> 2; mt < M_TILES; mt += 74) {
        int m0 = mt * 128;
        float C[2][4][4];
        #pragma unroll
        for (int it = 0; it < 2; it++)
            #pragma unroll
            for (int f = 0; f < 4; f++)
                #pragma unroll
                for (int q = 0; q < 4; q++) C[it][f][q] = 0.0f;

        load_achunk(sb, t, m0, 0);
        load_achunk(sb, t, m0, 1);
        load_achunk(sb, t, m0, 2);

        #pragma unroll 1
        for (int c = 0; c < 8; c++) {
            if (c < 6)      asm volatile("cp.async.wait_group 2;" ::: "memory");
            else if (c == 6) asm volatile("cp.async.wait_group 1;" ::: "memory");
            else             asm volatile("cp.async.wait_group 0;" ::: "memory");
            __syncthreads();
            uint32_t Ab = sb + SMEM_A_OFF + (c % A_BUFS) * 16384;

            #pragma unroll
            for (int kl = 0; kl < 2; kl++) {
                int ks = c * 2 + kl;
                uint32_t ah[2][4], al[2][4];
                #pragma unroll
                for (int it = 0; it < 2; it++) {
                    int uh = kl * 2 + uhiA;
                    uint32_t base = Ab + rowA[it] * 128;
                    ldsm4(ah[it], base + ((uh ^ xorA[it]) << 4));
                    ldsm4(al[it], base + (((uh + 4) ^ xorA[it]) << 4));
                }
                uint32_t bh[4][2], bl[4][2];
                #pragma unroll
                for (int g4 = 0; g4 < 2; g4++) {
                    int qb = ks * 2 + qloB;
                    uint32_t base = sb + rowB[g4] * 512 + ((qb ^ xorB[g4]) << 4);
                    uint32_t r[4];
                    ldsm4(r, base);
                    bh[2 * g4][0] = r[0]; bh[2 * g4][1] = r[1];
                    bh[2 * g4 + 1][0] = r[2]; bh[2 * g4 + 1][1] = r[3];
                    ldsm4(r, base + 32768);
                    bl[2 * g4][0] = r[0]; bl[2 * g4][1] = r[1];
                    bl[2 * g4 + 1][0] = r[2]; bl[2 * g4 + 1][1] = r[3];
                }
                #pragma unroll
                for (int it = 0; it < 2; it++)
                    #pragma unroll
                    for (int f = 0; f < 4; f++) {
                        mma16(C[it][f], ah[it], bh[f]);
                        mma16(C[it][f], ah[it], bl[f]);
                        mma16(C[it][f], al[it], bh[f]);
                    }
            }
            __syncthreads();
            if (c < 5) load_achunk(sb, t, m0, c + 3);
        }

        // epilogue: direct gmem stores
        #pragma unroll
        for (int it = 0; it < 2; it++) {
            int m = m0 + wm * 32 + it * 16 + (lane >> 2);
            #pragma unroll
            for (int f = 0; f < 4; f++) {
                int col = nq * 64 + wn * 32 + f * 8 + (lane & 3) * 2;
                if (m < N_NODES)
                    *(float2*)(out + (size_t)m * D + col) = make_float2(C[it][f][0], C[it][f][1]);
                if (m + 8 < N_NODES)
                    *(float2*)(out + (size_t)(m + 8) * D + col) = make_float2(C[it][f][2], C[it][f][3]);
            }
        }
    }
}

// ---------------- aggregation: gather over CSR ----------------------------------
// out[i] = bias + dis[i]^2 * hw[i] + sum_{e: dst=i} dis[i]*dis[src] * hw[src]
template<bool RELU, bool TO_SPLITS>
__global__ __launch_bounds__(256) void k_agg(const float* __restrict__ bias,
                                             float* __restrict__ out_ext) {
    int gw = (blockIdx.x * 256 + threadIdx.x) >> 5;
    int lane = threadIdx.x & 31;
    if (gw >= N_NODES) return;
    const float* hw = g_b;
    float dd = g_dis[gw];
    int c0 = lane * 8;
    const float4* hp = (const float4*)(hw + (size_t)gw * D + c0);
    float4 h0 = hp[0], h1 = hp[1];
    float4 bb0 = *(const float4*)(bias + c0);
    float4 bb1 = *(const float4*)(bias + c0 + 4);
    float sw = dd * dd;
    float v[8];
    v[0] = bb0.x + h0.x * sw; v[1] = bb0.y + h0.y * sw;
    v[2] = bb0.z + h0.z * sw; v[3] = bb0.w + h0.w * sw;
    v[4] = bb1.x + h1.x * sw; v[5] = bb1.y + h1.y * sw;
    v[6] = bb1.z + h1.z * sw; v[7] = bb1.w + h1.w * sw;
    int e = g_rowptr[gw], e1 = g_rowptr[gw + 1];
    for (; e + 1 < e1; e += 2) {
        int s0 = g_col[e], s1 = g_col[e + 1];
        float w0 = dd * g_dis[s0], w1 = dd * g_dis[s1];
        const float4* p0 = (const float4*)(hw + (size_t)s0 * D + c0);
        const float4* p1 = (const float4*)(hw + (size_t)s1 * D + c0);
        float4 x0 = p0[0], x1 = p0[1];
        float4 y0 = p1[0], y1 = p1[1];
        v[0] += x0.x * w0 + y0.x * w1; v[1] += x0.y * w0 + y0.y * w1;
        v[2] += x0.z * w0 + y0.z * w1; v[3] += x0.w * w0 + y0.w * w1;
        v[4] += x1.x * w0 + y1.x * w1; v[5] += x1.y * w0 + y1.y * w1;
        v[6] += x1.z * w0 + y1.z * w1; v[7] += x1.w * w0 + y1.w * w1;
    }
    if (e < e1) {
        int s0 = g_col[e];
        float w0 = dd * g_dis[s0];
        const float4* p0 = (const float4*)(hw + (size_t)s0 * D + c0);
        float4 x0 = p0[0], x1 = p0[1];
        v[0] += x0.x * w0; v[1] += x0.y * w0; v[2] += x0.z * w0; v[3] += x0.w * w0;
        v[4] += x1.x * w0; v[5] += x1.y * w0; v[6] += x1.z * w0; v[7] += x1.w * w0;
    }
    if (RELU) {
        #pragma unroll
        for (int i = 0; i < 8; i++) v[i] = fmaxf(v[i], 0.0f);
    }
    if (TO_SPLITS) {
        __align__(16) __nv_bfloat16 s0[8], s1[8];
        #pragma unroll
        for (int i = 0; i < 8; i++) split2(v[i], s0[i], s1[i]);
        size_t idx = (size_t)gw * D + c0;
        *(uint4*)&g_a0[idx] = *(const uint4*)s0;
        *(uint4*)&g_a1[idx] = *(const uint4*)s1;
    } else {
        float4* op = (float4*)(out_ext + (size_t)gw * D + c0);
        op[0] = make_float4(v[0], v[1], v[2], v[3]);
        op[1] = make_float4(v[4], v[5], v[6], v[7]);
    }
}

// ---------------- launch --------------------------------------------------------
extern "C" void kernel_launch(void* const* d_in, const int* in_sizes, int n_in,
                              void* d_out, int out_size) {
    const float* x       = (const float*)d_in[0];
    const int*   ei      = (const int*)d_in[1];
    const float* W_embed = (const float*)d_in[2];
    const float* b_embed = (const float*)d_in[3];
    const float* W1      = (const float*)d_in[4];
    const float* b1      = (const float*)d_in[5];
    const float* W2      = (const float*)d_in[6];
    const float* b2      = (const float*)d_in[7];
    float* out = (float*)d_out;

    cudaFuncSetAttribute(k_gemm_bf16, cudaFuncAttributeMaxDynamicSharedMemorySize, SMEM_GEMM);

    __nv_bfloat16* ws = nullptr;
    float* gb = nullptr;
    cudaGetSymbolAddress((void**)&ws, g_ws);
    cudaGetSymbolAddress((void**)&gb, g_b);

    int agg_blocks = (N_NODES * 32 + 255) / 256;
    int e4_blocks = (N_EDGES / 4 + 255) / 256;

    // slots 1-3: prep (gemm lands at slot 4 = ncu capture slot)
    k_prep<<<(D * D) / 256, 256>>>(W1, W2);
    k_count4<<<e4_blocks, 256>>>(ei);
    k_embed<<<(M_PAD + EMB_NODES - 1) / EMB_NODES, 256>>>(x, W_embed, b_embed);

    // layer 1 GEMM (slot 4)
    k_gemm_bf16<<<296, 256, SMEM_GEMM>>>(ws, gb);

    // CSR finish (independent of GEMM)
    k_scan_a<<<SCAN_BLKS, 1024>>>();
    k_scan_c<<<SCAN_BLKS, 1024>>>();
    k_fill4<<<e4_blocks, 256>>>(ei);

    // layer 1 aggregation -> splits for layer 2
    k_agg<true, true><<<agg_blocks, 256>>>(b1, nullptr);

    // layer 2
    k_gemm_bf16<<<296, 256, SMEM_GEMM>>>(ws + 2 * D * D, gb);
    k_agg<false, false><<<agg_blocks, 256>>>(b2, out);
}

// round 11
// speedup vs baseline: 1.6090x; 1.0225x over previous
#include <cuda_runtime.h>
#include <cuda_bf16.h>
#include <cstdint>

#define N_NODES 50000
#define N_EDGES 300000
#define D 256
#define F_IN 11
#define M_TILES 391
#define M_PAD (M_TILES * 128)

// ---------------- static scratch ------------------------------------------------
__device__ __align__(16) __nv_bfloat16 g_a0[(size_t)M_PAD * D];  // A hi split
__device__ __align__(16) __nv_bfloat16 g_a1[(size_t)M_PAD * D];  // A lo split
__device__ __align__(16) float g_b[(size_t)N_NODES * D];         // GEMM output fp32
__device__ __align__(16) __nv_bfloat16 g_ws[2][2][D * D];        // W splits [layer][split][n*256+k]
__device__ float g_dis[N_NODES];
__device__ int   g_cnt[N_NODES];
__device__ int   g_rowptr[N_NODES + 1];
__device__ int   g_cursor[N_NODES];
__device__ int   g_col[N_EDGES];
__device__ int   g_part[64];

// ---------------- helpers -------------------------------------------------------
__device__ __forceinline__ uint32_t smem_u32(const void* p) {
    uint32_t a;
    asm("{ .reg .u64 t; cvta.to.shared.u64 t, %1; cvt.u32.u64 %0, t; }" : "=r"(a) : "l"(p));
    return a;
}
__device__ __forceinline__ void cpa16(uint32_t d, const void* s) {
    asm volatile("cp.async.cg.shared.global [%0], [%1], 16;" :: "r"(d), "l"(s));
}
__device__ __forceinline__ void ldsm4(uint32_t* r, uint32_t a) {
    asm volatile("ldmatrix.sync.aligned.m8n8.x4.shared.b16 {%0,%1,%2,%3}, [%4];"
                 : "=r"(r[0]), "=r"(r[1]), "=r"(r[2]), "=r"(r[3]) : "r"(a));
}
__device__ __forceinline__ void mma16(float* c, const uint32_t* a, const uint32_t* b) {
    asm volatile("mma.sync.aligned.m16n8k16.row.col.f32.bf16.bf16.f32 "
                 "{%0,%1,%2,%3},{%4,%5,%6,%7},{%8,%9},{%0,%1,%2,%3};"
                 : "+f"(c[0]), "+f"(c[1]), "+f"(c[2]), "+f"(c[3])
                 : "r"(a[0]), "r"(a[1]), "r"(a[2]), "r"(a[3]), "r"(b[0]), "r"(b[1]));
}
__device__ __forceinline__ void split2(float x, __nv_bfloat16& s0, __nv_bfloat16& s1) {
    s0 = __float2bfloat16(x);
    s1 = __float2bfloat16(x - __bfloat162float(s0));
}

// ---------------- prep: weight split --------------------------------------------
__global__ void k_prep(const float* __restrict__ W1, const float* __restrict__ W2) {
    int i = blockIdx.x * 256 + threadIdx.x;   // i = k*256+n
    int k = i >> 8, n = i & 255;
    __nv_bfloat16 s0, s1;
    split2(W1[i], s0, s1);
    g_ws[0][0][n * 256 + k] = s0; g_ws[0][1][n * 256 + k] = s1;
    split2(W2[i], s0, s1);
    g_ws[1][0][n * 256 + k] = s0; g_ws[1][1][n * 256 + k] = s1;
}

// ---------------- CSR build -----------------------------------------------------
// g_cnt starts zero (static init on first call; re-zeroed by k_scan_c each call)
__global__ void k_count4(const int* __restrict__ ei) {
    int i = blockIdx.x * 256 + threadIdx.x;
    if (i < N_EDGES / 4) {
        int4 d = ((const int4*)(ei + N_EDGES))[i];
        atomicAdd(&g_cnt[d.x], 1);
        atomicAdd(&g_cnt[d.y], 1);
        atomicAdd(&g_cnt[d.z], 1);
        atomicAdd(&g_cnt[d.w], 1);
    }
}

#define SCAN_BLKS 49
__global__ __launch_bounds__(1024) void k_scan_a() {
    __shared__ int s[1024];
    int t = threadIdx.x, i = blockIdx.x * 1024 + t;
    int v = (i < N_NODES) ? g_cnt[i] : 0;
    s[t] = v;
    __syncthreads();
    #pragma unroll
    for (int off = 1; off < 1024; off <<= 1) {
        int tmp = (t >= off) ? s[t - off] : 0;
        __syncthreads();
        s[t] += tmp;
        __syncthreads();
    }
    if (i < N_NODES) g_rowptr[i] = s[t] - v;   // block-local exclusive
    if (t == 1023) g_part[blockIdx.x] = s[t];
}
__global__ __launch_bounds__(1024) void k_scan_c() {
    __shared__ int soff;
    int t = threadIdx.x, bid = blockIdx.x, i = bid * 1024 + t;
    if (t == 0) {
        int s = 0;
        for (int j = 0; j < bid; j++) s += g_part[j];
        soff = s;
    }
    __syncthreads();
    int off = soff;
    if (i < N_NODES) {
        int r = g_rowptr[i] + off;
        g_rowptr[i] = r;
        g_cursor[i] = r;
        g_dis[i] = rsqrtf((float)(g_cnt[i] + 1));
        g_cnt[i] = 0;                    // restore for next call (graph replay)
    }
    if (i == N_NODES) g_rowptr[N_NODES] = N_EDGES;
}
__global__ void k_fill4(const int* __restrict__ ei) {
    int i = blockIdx.x * 256 + threadIdx.x;
    if (i < N_EDGES / 4) {
        int4 s = ((const int4*)ei)[i];
        int4 d = ((const int4*)(ei + N_EDGES))[i];
        int p;
        p = atomicAdd(&g_cursor[d.x], 1); g_col[p] = s.x;
        p = atomicAdd(&g_cursor[d.y], 1); g_col[p] = s.y;
        p = atomicAdd(&g_cursor[d.z], 1); g_col[p] = s.z;
        p = atomicAdd(&g_cursor[d.w], 1); g_col[p] = s.w;
    }
}

// ---------------- embed: g_a0/g_a1 = split2(relu(x @ W_embed + b)), pad zeros ---
#define EMB_NODES 8
__global__ __launch_bounds__(256) void k_embed(const float* __restrict__ x,
                                               const float* __restrict__ W,
                                               const float* __restrict__ b) {
    __shared__ float Ws[F_IN * D];
    __shared__ float xs[EMB_NODES * F_IN];
    int t = threadIdx.x;
    for (int i = t; i < F_IN * D; i += 256) Ws[i] = W[i];
    int n0 = blockIdx.x * EMB_NODES;
    for (int i = t; i < EMB_NODES * F_IN; i += 256) {
        int node = n0 + i / F_IN;
        xs[i] = (node < N_NODES) ? x[(size_t)node * F_IN + (i % F_IN)] : 0.0f;
    }
    __syncthreads();
    float bv = b[t];
    #pragma unroll 1
    for (int j = 0; j < EMB_NODES; j++) {
        int node = n0 + j;
        if (node >= M_PAD) break;
        __nv_bfloat16 s0 = __float2bfloat16(0.0f), s1 = s0;
        if (node < N_NODES) {
            float acc = bv;
            #pragma unroll
            for (int k = 0; k < F_IN; k++) acc += xs[j * F_IN + k] * Ws[k * D + t];
            split2(fmaxf(acc, 0.0f), s0, s1);
        }
        size_t idx = (size_t)node * D + t;
        g_a0[idx] = s0;
        g_a1[idx] = s1;
    }
}

// ---------------- bf16x2 mma.sync GEMM, 2 CTAs/SM, 3-deep A ring ----------------
// grid 296 persistent CTAs: nq = cta&3 (N quarter, 64 cols), m-tiles stride 74.
// smem 112KB: B resident [2 spl][64 n][256 k] = 64KB at 0;
//             A ring: 3 bufs x [128 m][128B row: hi k32 64B | lo k32 64B] = 48KB.
// ONE barrier per chunk: prefetch for c+2 issued at top of chunk c, into the
// buffer ((c+2)%3 == (c-1)%3) that the top-of-c barrier just proved drained.
#define SMEM_A_OFF 65536
#define A_BUFS 3
#define SMEM_GEMM (SMEM_A_OFF + A_BUFS * 16384)   // 114688

__device__ __forceinline__ void load_achunk(uint32_t sb, int t, int m0, int c) {
    int k0 = c * 32;
    uint32_t ab = sb + SMEM_A_OFF + (c % A_BUFS) * 16384;
    #pragma unroll
    for (int j = 0; j < 4; j++) {
        int u = t + 256 * j;                  // 0..1023 16B units
        int row = u >> 3, uu = u & 7;         // uu<4: hi, else lo
        uint32_t dst = ab + row * 128 + ((uu ^ (row & 7)) << 4);
        const __nv_bfloat16* base = (uu < 4) ? g_a0 : g_a1;
        cpa16(dst, base + (size_t)(m0 + row) * D + k0 + (uu & 3) * 8);
    }
    asm volatile("cp.async.commit_group;" ::: "memory");
}

__global__ __launch_bounds__(256, 2) void k_gemm_bf16(const __nv_bfloat16* __restrict__ Wb,
                                                      float* __restrict__ out) {
    extern __shared__ __align__(1024) char smem[];
    const uint32_t sb = smem_u32(smem);
    const int t = threadIdx.x, wid = t >> 5, lane = t & 31;
    const int nq = blockIdx.x & 3;
    const int wm = wid & 3, wn = wid >> 2;
    const int dq = lane >> 3, Lr = lane & 7;

    // load resident B (quarter of W, both splits), one commit group
    #pragma unroll
    for (int j = 0; j < 16; j++) {
        int u = t + 256 * j;                  // 0..4095 16B units
        int s = u >> 11;
        int row = (u & 2047) >> 5;
        int q = u & 31;
        uint32_t dst = sb + s * 32768 + row * 512 + ((q ^ (row & 7)) << 4);
        cpa16(dst, Wb + s * (D * D) + (size_t)(nq * 64 + row) * D + q * 8);
    }
    asm volatile("cp.async.commit_group;" ::: "memory");

    // lane geometry
    int rowA[2], xorA[2];
    #pragma unroll
    for (int it = 0; it < 2; it++) {
        rowA[it] = wm * 32 + it * 16 + Lr + (dq & 1) * 8;
        xorA[it] = rowA[it] & 7;
    }
    const int uhiA = dq >> 1;
    int rowB[2], xorB[2];
    #pragma unroll
    for (int g4 = 0; g4 < 2; g4++) {
        rowB[g4] = wn * 32 + g4 * 16 + (dq >> 1) * 8 + Lr;
        xorB[g4] = rowB[g4] & 7;
    }
    const int qloB = dq & 1;

    #pragma unroll 1
    for (int mt = blockIdx.x >> 2; mt < M_TILES; mt += 74) {
        int m0 = mt * 128;
        float C[2][4][4];
        #pragma unroll
        for (int it = 0; it < 2; it++)
            #pragma unroll
            for (int f = 0; f < 4; f++)
                #pragma unroll
                for (int q = 0; q < 4; q++) C[it][f][q] = 0.0f;

        __syncthreads();                      // prev tile fully consumed by all warps
        load_achunk(sb, t, m0, 0);
        load_achunk(sb, t, m0, 1);

        #pragma unroll 1
        for (int c = 0; c < 8; c++) {
            if (c < 7) asm volatile("cp.async.wait_group 1;" ::: "memory");
            else       asm volatile("cp.async.wait_group 0;" ::: "memory");
            __syncthreads();
            if (c < 6) load_achunk(sb, t, m0, c + 2);   // into buffer (c-1)%3, just drained

            uint32_t Ab = sb + SMEM_A_OFF + (c % A_BUFS) * 16384;

            #pragma unroll
            for (int kl = 0; kl < 2; kl++) {
                int ks = c * 2 + kl;
                // A fragments (hi+lo)
                uint32_t ah[2][4], al[2][4];
                #pragma unroll
                for (int it = 0; it < 2; it++) {
                    int uh = kl * 2 + uhiA;
                    uint32_t base = Ab + rowA[it] * 128;
                    ldsm4(ah[it], base + ((uh ^ xorA[it]) << 4));
                    ldsm4(al[it], base + (((uh + 4) ^ xorA[it]) << 4));
                }
                // B hi fragments, then first mma burst (overlaps with B lo loads)
                uint32_t bh[4][2];
                #pragma unroll
                for (int g4 = 0; g4 < 2; g4++) {
                    int qb = ks * 2 + qloB;
                    uint32_t base = sb + rowB[g4] * 512 + ((qb ^ xorB[g4]) << 4);
                    uint32_t r[4];
                    ldsm4(r, base);
                    bh[2 * g4][0] = r[0]; bh[2 * g4][1] = r[1];
                    bh[2 * g4 + 1][0] = r[2]; bh[2 * g4 + 1][1] = r[3];
                }
                #pragma unroll
                for (int it = 0; it < 2; it++)
                    #pragma unroll
                    for (int f = 0; f < 4; f++)
                        mma16(C[it][f], ah[it], bh[f]);
                // B lo fragments + remaining bursts
                uint32_t bl[4][2];
                #pragma unroll
                for (int g4 = 0; g4 < 2; g4++) {
                    int qb = ks * 2 + qloB;
                    uint32_t base = sb + rowB[g4] * 512 + 32768 + ((qb ^ xorB[g4]) << 4);
                    uint32_t r[4];
                    ldsm4(r, base);
                    bl[2 * g4][0] = r[0]; bl[2 * g4][1] = r[1];
                    bl[2 * g4 + 1][0] = r[2]; bl[2 * g4 + 1][1] = r[3];
                }
                #pragma unroll
                for (int it = 0; it < 2; it++)
                    #pragma unroll
                    for (int f = 0; f < 4; f++) {
                        mma16(C[it][f], ah[it], bl[f]);
                        mma16(C[it][f], al[it], bh[f]);
                    }
            }
        }

        // epilogue: direct gmem stores
        #pragma unroll
        for (int it = 0; it < 2; it++) {
            int m = m0 + wm * 32 + it * 16 + (lane >> 2);
            #pragma unroll
            for (int f = 0; f < 4; f++) {
                int col = nq * 64 + wn * 32 + f * 8 + (lane & 3) * 2;
                if (m < N_NODES)
                    *(float2*)(out + (size_t)m * D + col) = make_float2(C[it][f][0], C[it][f][1]);
                if (m + 8 < N_NODES)
                    *(float2*)(out + (size_t)(m + 8) * D + col) = make_float2(C[it][f][2], C[it][f][3]);
            }
        }
    }
}

// ---------------- aggregation: gather over CSR ----------------------------------
// out[i] = bias + dis[i]^2 * hw[i] + sum_{e: dst=i} dis[i]*dis[src] * hw[src]
template<bool RELU, bool TO_SPLITS>
__global__ __launch_bounds__(256) void k_agg(const float* __restrict__ bias,
                                             float* __restrict__ out_ext) {
    int gw = (blockIdx.x * 256 + threadIdx.x) >> 5;
    int lane = threadIdx.x & 31;
    if (gw >= N_NODES) return;
    const float* hw = g_b;
    float dd = g_dis[gw];
    int c0 = lane * 8;
    const float4* hp = (const float4*)(hw + (size_t)gw * D + c0);
    float4 h0 = hp[0], h1 = hp[1];
    float4 bb0 = *(const float4*)(bias + c0);
    float4 bb1 = *(const float4*)(bias + c0 + 4);
    float sw = dd * dd;
    float v[8];
    v[0] = bb0.x + h0.x * sw; v[1] = bb0.y + h0.y * sw;
    v[2] = bb0.z + h0.z * sw; v[3] = bb0.w + h0.w * sw;
    v[4] = bb1.x + h1.x * sw; v[5] = bb1.y + h1.y * sw;
    v[6] = bb1.z + h1.z * sw; v[7] = bb1.w + h1.w * sw;
    int e = g_rowptr[gw], e1 = g_rowptr[gw + 1];
    for (; e + 1 < e1; e += 2) {
        int s0 = g_col[e], s1 = g_col[e + 1];
        float w0 = dd * g_dis[s0], w1 = dd * g_dis[s1];
        const float4* p0 = (const float4*)(hw + (size_t)s0 * D + c0);
        const float4* p1 = (const float4*)(hw + (size_t)s1 * D + c0);
        float4 x0 = p0[0], x1 = p0[1];
        float4 y0 = p1[0], y1 = p1[1];
        v[0] += x0.x * w0 + y0.x * w1; v[1] += x0.y * w0 + y0.y * w1;
        v[2] += x0.z * w0 + y0.z * w1; v[3] += x0.w * w0 + y0.w * w1;
        v[4] += x1.x * w0 + y1.x * w1; v[5] += x1.y * w0 + y1.y * w1;
        v[6] += x1.z * w0 + y1.z * w1; v[7] += x1.w * w0 + y1.w * w1;
    }
    if (e < e1) {
        int s0 = g_col[e];
        float w0 = dd * g_dis[s0];
        const float4* p0 = (const float4*)(hw + (size_t)s0 * D + c0);
        float4 x0 = p0[0], x1 = p0[1];
        v[0] += x0.x * w0; v[1] += x0.y * w0; v[2] += x0.z * w0; v[3] += x0.w * w0;
        v[4] += x1.x * w0; v[5] += x1.y * w0; v[6] += x1.z * w0; v[7] += x1.w * w0;
    }
    if (RELU) {
        #pragma unroll
        for (int i = 0; i < 8; i++) v[i] = fmaxf(v[i], 0.0f);
    }
    if (TO_SPLITS) {
        __align__(16) __nv_bfloat16 s0[8], s1[8];
        #pragma unroll
        for (int i = 0; i < 8; i++) split2(v[i], s0[i], s1[i]);
        size_t idx = (size_t)gw * D + c0;
        *(uint4*)&g_a0[idx] = *(const uint4*)s0;
        *(uint4*)&g_a1[idx] = *(const uint4*)s1;
    } else {
        float4* op = (float4*)(out_ext + (size_t)gw * D + c0);
        op[0] = make_float4(v[0], v[1], v[2], v[3]);
        op[1] = make_float4(v[4], v[5], v[6], v[7]);
    }
}

// ---------------- launch --------------------------------------------------------
extern "C" void kernel_launch(void* const* d_in, const int* in_sizes, int n_in,
                              void* d_out, int out_size) {
    const float* x       = (const float*)d_in[0];
    const int*   ei      = (const int*)d_in[1];
    const float* W_embed = (const float*)d_in[2];
    const float* b_embed = (const float*)d_in[3];
    const float* W1      = (const float*)d_in[4];
    const float* b1      = (const float*)d_in[5];
    const float* W2      = (const float*)d_in[6];
    const float* b2      = (const float*)d_in[7];
    float* out = (float*)d_out;

    cudaFuncSetAttribute(k_gemm_bf16, cudaFuncAttributeMaxDynamicSharedMemorySize, SMEM_GEMM);

    __nv_bfloat16* ws = nullptr;
    float* gb = nullptr;
    cudaGetSymbolAddress((void**)&ws, g_ws);
    cudaGetSymbolAddress((void**)&gb, g_b);

    int agg_blocks = (N_NODES * 32 + 255) / 256;
    int e4_blocks = (N_EDGES / 4 + 255) / 256;

    // slots 1-3: prep (gemm lands at slot 4 = ncu capture slot)
    k_prep<<<(D * D) / 256, 256>>>(W1, W2);
    k_count4<<<e4_blocks, 256>>>(ei);
    k_embed<<<(M_PAD + EMB_NODES - 1) / EMB_NODES, 256>>>(x, W_embed, b_embed);

    // layer 1 GEMM (slot 4)
    k_gemm_bf16<<<296, 256, SMEM_GEMM>>>(ws, gb);

    // CSR finish (independent of GEMM)
    k_scan_a<<<SCAN_BLKS, 1024>>>();
    k_scan_c<<<SCAN_BLKS, 1024>>>();
    k_fill4<<<e4_blocks, 256>>>(ei);

    // layer 1 aggregation -> splits for layer 2
    k_agg<true, true><<<agg_blocks, 256>>>(b1, nullptr);

    // layer 2
    k_gemm_bf16<<<296, 256, SMEM_GEMM>>>(ws + 2 * D * D, gb);
    k_agg<false, false><<<agg_blocks, 256>>>(b2, out);
}

// round 13
// speedup vs baseline: 1.6551x; 1.0287x over previous
#include <cuda_runtime.h>
#include <cuda_bf16.h>
#include <cstdint>

#define N_NODES 50000
#define N_EDGES 300000
#define D 256
#define F_IN 11
#define M_TILES 391
#define M_PAD (M_TILES * 128)

// ---------------- static scratch ------------------------------------------------
__device__ __align__(16) __nv_bfloat16 g_a0[(size_t)M_PAD * D];  // A hi split
__device__ __align__(16) __nv_bfloat16 g_a1[(size_t)M_PAD * D];  // A lo split
__device__ __align__(16) float g_b[(size_t)N_NODES * D];         // GEMM output fp32
__device__ __align__(16) __nv_bfloat16 g_ws[2][2][D * D];        // W splits [layer][split][n*256+k]
__device__ float g_dis[N_NODES];
__device__ int   g_cnt[N_NODES];
__device__ int   g_rowptr[N_NODES + 1];
__device__ int   g_cursor[N_NODES];
__device__ int   g_col[N_EDGES];
__device__ int   g_part[64];

// ---------------- helpers -------------------------------------------------------
__device__ __forceinline__ uint32_t smem_u32(const void* p) {
    uint32_t a;
    asm("{ .reg .u64 t; cvta.to.shared.u64 t, %1; cvt.u32.u64 %0, t; }" : "=r"(a) : "l"(p));
    return a;
}
__device__ __forceinline__ void cpa16(uint32_t d, const void* s) {
    asm volatile("cp.async.cg.shared.global [%0], [%1], 16;" :: "r"(d), "l"(s));
}
__device__ __forceinline__ void ldsm4(uint32_t* r, uint32_t a) {
    asm volatile("ldmatrix.sync.aligned.m8n8.x4.shared.b16 {%0,%1,%2,%3}, [%4];"
                 : "=r"(r[0]), "=r"(r[1]), "=r"(r[2]), "=r"(r[3]) : "r"(a));
}
__device__ __forceinline__ void mma16(float* c, const uint32_t* a, const uint32_t* b) {
    asm volatile("mma.sync.aligned.m16n8k16.row.col.f32.bf16.bf16.f32 "
                 "{%0,%1,%2,%3},{%4,%5,%6,%7},{%8,%9},{%0,%1,%2,%3};"
                 : "+f"(c[0]), "+f"(c[1]), "+f"(c[2]), "+f"(c[3])
                 : "r"(a[0]), "r"(a[1]), "r"(a[2]), "r"(a[3]), "r"(b[0]), "r"(b[1]));
}
__device__ __forceinline__ void split2(float x, __nv_bfloat16& s0, __nv_bfloat16& s1) {
    s0 = __float2bfloat16(x);
    s1 = __float2bfloat16(x - __bfloat162float(s0));
}

// ---------------- prep: weight split --------------------------------------------
__global__ void k_prep(const float* __restrict__ W1, const float* __restrict__ W2) {
    int i = blockIdx.x * 256 + threadIdx.x;   // i = k*256+n
    int k = i >> 8, n = i & 255;
    __nv_bfloat16 s0, s1;
    split2(W1[i], s0, s1);
    g_ws[0][0][n * 256 + k] = s0; g_ws[0][1][n * 256 + k] = s1;
    split2(W2[i], s0, s1);
    g_ws[1][0][n * 256 + k] = s0; g_ws[1][1][n * 256 + k] = s1;
}

// ---------------- CSR build -----------------------------------------------------
// g_cnt starts zero (static init on first call; re-zeroed by k_scan_c each call)
__global__ void k_count4(const int* __restrict__ ei) {
    int i = blockIdx.x * 256 + threadIdx.x;
    if (i < N_EDGES / 4) {
        int4 d = ((const int4*)(ei + N_EDGES))[i];
        atomicAdd(&g_cnt[d.x], 1);
        atomicAdd(&g_cnt[d.y], 1);
        atomicAdd(&g_cnt[d.z], 1);
        atomicAdd(&g_cnt[d.w], 1);
    }
}

#define SCAN_BLKS 49
__global__ __launch_bounds__(1024) void k_scan_a() {
    __shared__ int s[1024];
    int t = threadIdx.x, i = blockIdx.x * 1024 + t;
    int v = (i < N_NODES) ? g_cnt[i] : 0;
    s[t] = v;
    __syncthreads();
    #pragma unroll
    for (int off = 1; off < 1024; off <<= 1) {
        int tmp = (t >= off) ? s[t - off] : 0;
        __syncthreads();
        s[t] += tmp;
        __syncthreads();
    }
    if (i < N_NODES) g_rowptr[i] = s[t] - v;   // block-local exclusive
    if (t == 1023) g_part[blockIdx.x] = s[t];
}
__global__ __launch_bounds__(1024) void k_scan_c() {
    __shared__ int soff;
    int t = threadIdx.x, bid = blockIdx.x, i = bid * 1024 + t;
    if (t == 0) {
        int s = 0;
        for (int j = 0; j < bid; j++) s += g_part[j];
        soff = s;
    }
    __syncthreads();
    int off = soff;
    if (i < N_NODES) {
        int r = g_rowptr[i] + off;
        g_rowptr[i] = r;
        g_cursor[i] = r;
        g_dis[i] = rsqrtf((float)(g_cnt[i] + 1));
        g_cnt[i] = 0;                    // restore for next call (graph replay)
    }
    if (i == N_NODES) g_rowptr[N_NODES] = N_EDGES;
}
__global__ void k_fill4(const int* __restrict__ ei) {
    int i = blockIdx.x * 256 + threadIdx.x;
    if (i < N_EDGES / 4) {
        int4 s = ((const int4*)ei)[i];
        int4 d = ((const int4*)(ei + N_EDGES))[i];
        int p;
        p = atomicAdd(&g_cursor[d.x], 1); g_col[p] = s.x;
        p = atomicAdd(&g_cursor[d.y], 1); g_col[p] = s.y;
        p = atomicAdd(&g_cursor[d.z], 1); g_col[p] = s.z;
        p = atomicAdd(&g_cursor[d.w], 1); g_col[p] = s.w;
    }
}

// ---------------- embed: g_a0/g_a1 = split2(relu(x @ W_embed + b)), pad zeros ---
#define EMB_NODES 8
__global__ __launch_bounds__(256) void k_embed(const float* __restrict__ x,
                                               const float* __restrict__ W,
                                               const float* __restrict__ b) {
    __shared__ float Ws[F_IN * D];
    __shared__ float xs[EMB_NODES * F_IN];
    int t = threadIdx.x;
    for (int i = t; i < F_IN * D; i += 256) Ws[i] = W[i];
    int n0 = blockIdx.x * EMB_NODES;
    for (int i = t; i < EMB_NODES * F_IN; i += 256) {
        int node = n0 + i / F_IN;
        xs[i] = (node < N_NODES) ? x[(size_t)node * F_IN + (i % F_IN)] : 0.0f;
    }
    __syncthreads();
    float bv = b[t];
    #pragma unroll 1
    for (int j = 0; j < EMB_NODES; j++) {
        int node = n0 + j;
        if (node >= M_PAD) break;
        __nv_bfloat16 s0 = __float2bfloat16(0.0f), s1 = s0;
        if (node < N_NODES) {
            float acc = bv;
            #pragma unroll
            for (int k = 0; k < F_IN; k++) acc += xs[j * F_IN + k] * Ws[k * D + t];
            split2(fmaxf(acc, 0.0f), s0, s1);
        }
        size_t idx = (size_t)node * D + t;
        g_a0[idx] = s0;
        g_a1[idx] = s1;
    }
}

// ---------------- bf16x2 mma.sync GEMM, 2 CTAs/SM, 3-deep A ring ----------------
// (identical to the proven 244.4us kernel)
#define SMEM_A_OFF 65536
#define A_BUFS 3
#define SMEM_GEMM (SMEM_A_OFF + A_BUFS * 16384)   // 114688

__device__ __forceinline__ void load_achunk(uint32_t sb, int t, int m0, int c) {
    int k0 = c * 32;
    uint32_t ab = sb + SMEM_A_OFF + (c % A_BUFS) * 16384;
    #pragma unroll
    for (int j = 0; j < 4; j++) {
        int u = t + 256 * j;                  // 0..1023 16B units
        int row = u >> 3, uu = u & 7;         // uu<4: hi, else lo
        uint32_t dst = ab + row * 128 + ((uu ^ (row & 7)) << 4);
        const __nv_bfloat16* base = (uu < 4) ? g_a0 : g_a1;
        cpa16(dst, base + (size_t)(m0 + row) * D + k0 + (uu & 3) * 8);
    }
    asm volatile("cp.async.commit_group;" ::: "memory");
}

__global__ __launch_bounds__(256, 2) void k_gemm_bf16(const __nv_bfloat16* __restrict__ Wb,
                                                      float* __restrict__ out) {
    extern __shared__ __align__(1024) char smem[];
    const uint32_t sb = smem_u32(smem);
    const int t = threadIdx.x, wid = t >> 5, lane = t & 31;
    const int nq = blockIdx.x & 3;
    const int wm = wid & 3, wn = wid >> 2;
    const int dq = lane >> 3, Lr = lane & 7;

    // load resident B (quarter of W, both splits), one commit group
    #pragma unroll
    for (int j = 0; j < 16; j++) {
        int u = t + 256 * j;                  // 0..4095 16B units
        int s = u >> 11;
        int row = (u & 2047) >> 5;
        int q = u & 31;
        uint32_t dst = sb + s * 32768 + row * 512 + ((q ^ (row & 7)) << 4);
        cpa16(dst, Wb + s * (D * D) + (size_t)(nq * 64 + row) * D + q * 8);
    }
    asm volatile("cp.async.commit_group;" ::: "memory");

    // lane geometry
    int rowA[2], xorA[2];
    #pragma unroll
    for (int it = 0; it < 2; it++) {
        rowA[it] = wm * 32 + it * 16 + Lr + (dq & 1) * 8;
        xorA[it] = rowA[it] & 7;
    }
    const int uhiA = dq >> 1;
    int rowB[2], xorB[2];
    #pragma unroll
    for (int g4 = 0; g4 < 2; g4++) {
        rowB[g4] = wn * 32 + g4 * 16 + (dq >> 1) * 8 + Lr;
        xorB[g4] = rowB[g4] & 7;
    }
    const int qloB = dq & 1;

    #pragma unroll 1
    for (int mt = blockIdx.x >> 2; mt < M_TILES; mt += 74) {
        int m0 = mt * 128;
        float C[2][4][4];
        #pragma unroll
        for (int it = 0; it < 2; it++)
            #pragma unroll
            for (int f = 0; f < 4; f++)
                #pragma unroll
                for (int q = 0; q < 4; q++) C[it][f][q] = 0.0f;

        __syncthreads();                      // prev tile fully consumed by all warps
        load_achunk(sb, t, m0, 0);
        load_achunk(sb, t, m0, 1);

        #pragma unroll 1
        for (int c = 0; c < 8; c++) {
            if (c < 7) asm volatile("cp.async.wait_group 1;" ::: "memory");
            else       asm volatile("cp.async.wait_group 0;" ::: "memory");
            __syncthreads();
            if (c < 6) load_achunk(sb, t, m0, c + 2);   // into buffer (c-1)%3, just drained

            uint32_t Ab = sb + SMEM_A_OFF + (c % A_BUFS) * 16384;

            #pragma unroll
            for (int kl = 0; kl < 2; kl++) {
                int ks = c * 2 + kl;
                uint32_t ah[2][4], al[2][4];
                #pragma unroll
                for (int it = 0; it < 2; it++) {
                    int uh = kl * 2 + uhiA;
                    uint32_t base = Ab + rowA[it] * 128;
                    ldsm4(ah[it], base + ((uh ^ xorA[it]) << 4));
                    ldsm4(al[it], base + (((uh + 4) ^ xorA[it]) << 4));
                }
                uint32_t bh[4][2];
                #pragma unroll
                for (int g4 = 0; g4 < 2; g4++) {
                    int qb = ks * 2 + qloB;
                    uint32_t base = sb + rowB[g4] * 512 + ((qb ^ xorB[g4]) << 4);
                    uint32_t r[4];
                    ldsm4(r, base);
                    bh[2 * g4][0] = r[0]; bh[2 * g4][1] = r[1];
                    bh[2 * g4 + 1][0] = r[2]; bh[2 * g4 + 1][1] = r[3];
                }
                #pragma unroll
                for (int it = 0; it < 2; it++)
                    #pragma unroll
                    for (int f = 0; f < 4; f++)
                        mma16(C[it][f], ah[it], bh[f]);
                uint32_t bl[4][2];
                #pragma unroll
                for (int g4 = 0; g4 < 2; g4++) {
                    int qb = ks * 2 + qloB;
                    uint32_t base = sb + rowB[g4] * 512 + 32768 + ((qb ^ xorB[g4]) << 4);
                    uint32_t r[4];
                    ldsm4(r, base);
                    bl[2 * g4][0] = r[0]; bl[2 * g4][1] = r[1];
                    bl[2 * g4 + 1][0] = r[2]; bl[2 * g4 + 1][1] = r[3];
                }
                #pragma unroll
                for (int it = 0; it < 2; it++)
                    #pragma unroll
                    for (int f = 0; f < 4; f++) {
                        mma16(C[it][f], ah[it], bl[f]);
                        mma16(C[it][f], al[it], bh[f]);
                    }
            }
        }

        // epilogue: direct gmem stores
        #pragma unroll
        for (int it = 0; it < 2; it++) {
            int m = m0 + wm * 32 + it * 16 + (lane >> 2);
            #pragma unroll
            for (int f = 0; f < 4; f++) {
                int col = nq * 64 + wn * 32 + f * 8 + (lane & 3) * 2;
                if (m < N_NODES)
                    *(float2*)(out + (size_t)m * D + col) = make_float2(C[it][f][0], C[it][f][1]);
                if (m + 8 < N_NODES)
                    *(float2*)(out + (size_t)(m + 8) * D + col) = make_float2(C[it][f][2], C[it][f][3]);
            }
        }
    }
}

// ---------------- aggregation: gather over CSR ----------------------------------
// out[i] = bias + dis[i]^2 * hw[i] + sum_{e: dst=i} dis[i]*dis[src] * hw[src]
template<bool RELU, bool TO_SPLITS>
__global__ __launch_bounds__(256) void k_agg(const float* __restrict__ bias,
                                             float* __restrict__ out_ext) {
    int gw = (blockIdx.x * 256 + threadIdx.x) >> 5;
    int lane = threadIdx.x & 31;
    if (gw >= N_NODES) return;
    const float* hw = g_b;
    float dd = g_dis[gw];
    int c0 = lane * 8;
    const float4* hp = (const float4*)(hw + (size_t)gw * D + c0);
    float4 h0 = hp[0], h1 = hp[1];
    float4 bb0 = *(const float4*)(bias + c0);
    float4 bb1 = *(const float4*)(bias + c0 + 4);
    float sw = dd * dd;
    float v[8];
    v[0] = bb0.x + h0.x * sw; v[1] = bb0.y + h0.y * sw;
    v[2] = bb0.z + h0.z * sw; v[3] = bb0.w + h0.w * sw;
    v[4] = bb1.x + h1.x * sw; v[5] = bb1.y + h1.y * sw;
    v[6] = bb1.z + h1.z * sw; v[7] = bb1.w + h1.w * sw;
    int e = g_rowptr[gw], e1 = g_rowptr[gw + 1];
    for (; e + 1 < e1; e += 2) {
        int s0 = g_col[e], s1 = g_col[e + 1];
        float w0 = dd * g_dis[s0], w1 = dd * g_dis[s1];
        const float4* p0 = (const float4*)(hw + (size_t)s0 * D + c0);
        const float4* p1 = (const float4*)(hw + (size_t)s1 * D + c0);
        float4 x0 = p0[0], x1 = p0[1];
        float4 y0 = p1[0], y1 = p1[1];
        v[0] += x0.x * w0 + y0.x * w1; v[1] += x0.y * w0 + y0.y * w1;
        v[2] += x0.z * w0 + y0.z * w1; v[3] += x0.w * w0 + y0.w * w1;
        v[4] += x1.x * w0 + y1.x * w1; v[5] += x1.y * w0 + y1.y * w1;
        v[6] += x1.z * w0 + y1.z * w1; v[7] += x1.w * w0 + y1.w * w1;
    }
    if (e < e1) {
        int s0 = g_col[e];
        float w0 = dd * g_dis[s0];
        const float4* p0 = (const float4*)(hw + (size_t)s0 * D + c0);
        float4 x0 = p0[0], x1 = p0[1];
        v[0] += x0.x * w0; v[1] += x0.y * w0; v[2] += x0.z * w0; v[3] += x0.w * w0;
        v[4] += x1.x * w0; v[5] += x1.y * w0; v[6] += x1.z * w0; v[7] += x1.w * w0;
    }
    if (RELU) {
        #pragma unroll
        for (int i = 0; i < 8; i++) v[i] = fmaxf(v[i], 0.0f);
    }
    if (TO_SPLITS) {
        __align__(16) __nv_bfloat16 s0[8], s1[8];
        #pragma unroll
        for (int i = 0; i < 8; i++) split2(v[i], s0[i], s1[i]);
        size_t idx = (size_t)gw * D + c0;
        *(uint4*)&g_a0[idx] = *(const uint4*)s0;
        *(uint4*)&g_a1[idx] = *(const uint4*)s1;
    } else {
        float4* op = (float4*)(out_ext + (size_t)gw * D + c0);
        op[0] = make_float4(v[0], v[1], v[2], v[3]);
        op[1] = make_float4(v[4], v[5], v[6], v[7]);
    }
}

// ---------------- launch --------------------------------------------------------
extern "C" void kernel_launch(void* const* d_in, const int* in_sizes, int n_in,
                              void* d_out, int out_size) {
    const float* x       = (const float*)d_in[0];
    const int*   ei      = (const int*)d_in[1];
    const float* W_embed = (const float*)d_in[2];
    const float* b_embed = (const float*)d_in[3];
    const float* W1      = (const float*)d_in[4];
    const float* b1      = (const float*)d_in[5];
    const float* W2      = (const float*)d_in[6];
    const float* b2      = (const float*)d_in[7];
    float* out = (float*)d_out;

    cudaFuncSetAttribute(k_gemm_bf16, cudaFuncAttributeMaxDynamicSharedMemorySize, SMEM_GEMM);

    __nv_bfloat16* ws = nullptr;
    float* gb = nullptr;
    cudaGetSymbolAddress((void**)&ws, g_ws);
    cudaGetSymbolAddress((void**)&gb, g_b);

    int agg_blocks = (N_NODES * 32 + 255) / 256;
    int e4_blocks = (N_EDGES / 4 + 255) / 256;

    // fork/join streams: CSR chain overlaps GEMM1. Created fresh per call (no
    // static state, deterministic work). If creation is rejected (e.g. under a
    // strict capture mode), fall back to fully serial on the capture stream —
    // which is exactly the proven 244us configuration.
    cudaStream_t side = 0;
    cudaEvent_t ev_fork = nullptr, ev_join = nullptr;
    bool forked =
        (cudaStreamCreateWithFlags(&side, cudaStreamNonBlocking) == cudaSuccess) &&
        (cudaEventCreateWithFlags(&ev_fork, cudaEventDisableTiming) == cudaSuccess) &&
        (cudaEventCreateWithFlags(&ev_join, cudaEventDisableTiming) == cudaSuccess);
    if (!forked) side = 0;

    // main: prep(1), embed(2)
    k_prep<<<(D * D) / 256, 256>>>(W1, W2);
    k_embed<<<(M_PAD + EMB_NODES - 1) / EMB_NODES, 256>>>(x, W_embed, b_embed);

    if (forked) {
        cudaEventRecord(ev_fork, 0);
        cudaStreamWaitEvent(side, ev_fork, 0);
    }

    // side: CSR chain (concurrent with GEMM1 when forked)
    k_count4<<<e4_blocks, 256, 0, side>>>(ei);                       // (3)

    // main: layer 1 GEMM (4th kernel launch in code order = ncu capture slot)
    k_gemm_bf16<<<296, 256, SMEM_GEMM>>>(ws, gb);

    k_scan_a<<<SCAN_BLKS, 1024, 0, side>>>();
    k_scan_c<<<SCAN_BLKS, 1024, 0, side>>>();
    k_fill4<<<e4_blocks, 256, 0, side>>>(ei);

    if (forked) {
        cudaEventRecord(ev_join, side);
        cudaStreamWaitEvent(0, ev_join, 0);   // join: agg needs GEMM1 + CSR
    }

    // layer 1 aggregation -> splits for layer 2
    k_agg<true, true><<<agg_blocks, 256>>>(b1, nullptr);

    // layer 2
    k_gemm_bf16<<<296, 256, SMEM_GEMM>>>(ws + 2 * D * D, gb);
    k_agg<false, false><<<agg_blocks, 256>>>(b2, out);
}

// round 15
// speedup vs baseline: 1.6554x; 1.0001x over previous
#include <cuda_runtime.h>
#include <cuda_bf16.h>
#include <cstdint>

#define N_NODES 50000
#define N_EDGES 300000
#define D 256
#define F_IN 11
#define M_TILES 391
#define M_PAD (M_TILES * 128)

// ---------------- static scratch ------------------------------------------------
__device__ __align__(16) __nv_bfloat16 g_a0[(size_t)M_PAD * D];  // A hi split
__device__ __align__(16) __nv_bfloat16 g_a1[(size_t)M_PAD * D];  // A lo split
__device__ __align__(16) float g_b[(size_t)N_NODES * D];         // GEMM output fp32
__device__ __align__(16) __nv_bfloat16 g_ws[2][2][D * D];        // W splits [layer][split][n*256+k]
__device__ float g_dis[N_NODES];
__device__ int   g_cnt[N_NODES];
__device__ int   g_rowptr[N_NODES + 1];
__device__ int   g_cursor[N_NODES];
__device__ int   g_col[N_EDGES];
__device__ int   g_part[64];

// ---------------- helpers -------------------------------------------------------
__device__ __forceinline__ uint32_t smem_u32(const void* p) {
    uint32_t a;
    asm("{ .reg .u64 t; cvta.to.shared.u64 t, %1; cvt.u32.u64 %0, t; }" : "=r"(a) : "l"(p));
    return a;
}
__device__ __forceinline__ void cpa16(uint32_t d, const void* s) {
    asm volatile("cp.async.cg.shared.global [%0], [%1], 16;" :: "r"(d), "l"(s));
}
__device__ __forceinline__ void ldsm4(uint32_t* r, uint32_t a) {
    asm volatile("ldmatrix.sync.aligned.m8n8.x4.shared.b16 {%0,%1,%2,%3}, [%4];"
                 : "=r"(r[0]), "=r"(r[1]), "=r"(r[2]), "=r"(r[3]) : "r"(a));
}
__device__ __forceinline__ void mma16(float* c, const uint32_t* a, const uint32_t* b) {
    asm volatile("mma.sync.aligned.m16n8k16.row.col.f32.bf16.bf16.f32 "
                 "{%0,%1,%2,%3},{%4,%5,%6,%7},{%8,%9},{%0,%1,%2,%3};"
                 : "+f"(c[0]), "+f"(c[1]), "+f"(c[2]), "+f"(c[3])
                 : "r"(a[0]), "r"(a[1]), "r"(a[2]), "r"(a[3]), "r"(b[0]), "r"(b[1]));
}
__device__ __forceinline__ void split2(float x, __nv_bfloat16& s0, __nv_bfloat16& s1) {
    s0 = __float2bfloat16(x);
    s1 = __float2bfloat16(x - __bfloat162float(s0));
}

// ---------------- CSR build -----------------------------------------------------
// g_cnt starts zero (static init on first call; re-zeroed by k_scan_c each call)
__global__ void k_count4(const int* __restrict__ ei) {
    int i = blockIdx.x * 256 + threadIdx.x;
    if (i < N_EDGES / 4) {
        int4 d = ((const int4*)(ei + N_EDGES))[i];
        atomicAdd(&g_cnt[d.x], 1);
        atomicAdd(&g_cnt[d.y], 1);
        atomicAdd(&g_cnt[d.z], 1);
        atomicAdd(&g_cnt[d.w], 1);
    }
}

#define SCAN_BLKS 49
__global__ __launch_bounds__(1024) void k_scan_a() {
    __shared__ int s[1024];
    int t = threadIdx.x, i = blockIdx.x * 1024 + t;
    int v = (i < N_NODES) ? g_cnt[i] : 0;
    s[t] = v;
    __syncthreads();
    #pragma unroll
    for (int off = 1; off < 1024; off <<= 1) {
        int tmp = (t >= off) ? s[t - off] : 0;
        __syncthreads();
        s[t] += tmp;
        __syncthreads();
    }
    if (i < N_NODES) g_rowptr[i] = s[t] - v;   // block-local exclusive
    if (t == 1023) g_part[blockIdx.x] = s[t];
}
__global__ __launch_bounds__(1024) void k_scan_c() {
    __shared__ int soff;
    int t = threadIdx.x, bid = blockIdx.x, i = bid * 1024 + t;
    if (t == 0) {
        int s = 0;
        for (int j = 0; j < bid; j++) s += g_part[j];
        soff = s;
    }
    __syncthreads();
    int off = soff;
    if (i < N_NODES) {
        int r = g_rowptr[i] + off;
        g_rowptr[i] = r;
        g_cursor[i] = r;
        g_dis[i] = rsqrtf((float)(g_cnt[i] + 1));
        g_cnt[i] = 0;                    // restore for next call (graph replay)
    }
    if (i == N_NODES) g_rowptr[N_NODES] = N_EDGES;
}
__global__ void k_fill4(const int* __restrict__ ei) {
    int i = blockIdx.x * 256 + threadIdx.x;
    if (i < N_EDGES / 4) {
        int4 s = ((const int4*)ei)[i];
        int4 d = ((const int4*)(ei + N_EDGES))[i];
        int p;
        p = atomicAdd(&g_cursor[d.x], 1); g_col[p] = s.x;
        p = atomicAdd(&g_cursor[d.y], 1); g_col[p] = s.y;
        p = atomicAdd(&g_cursor[d.z], 1); g_col[p] = s.z;
        p = atomicAdd(&g_cursor[d.w], 1); g_col[p] = s.w;
    }
}

// ---------------- embed + weight-split (merged, branch on blockIdx) -------------
#define EMB_NODES 8
#define EMB_BLOCKS ((M_PAD + EMB_NODES - 1) / EMB_NODES)
__global__ __launch_bounds__(256) void k_embed(const float* __restrict__ x,
                                               const float* __restrict__ W,
                                               const float* __restrict__ b,
                                               const float* __restrict__ W1,
                                               const float* __restrict__ W2) {
    int t = threadIdx.x;
    if (blockIdx.x >= EMB_BLOCKS) {
        // weight split: one block per 256 elements
        int i = (blockIdx.x - EMB_BLOCKS) * 256 + t;   // i = k*256+n
        int k = i >> 8, n = i & 255;
        __nv_bfloat16 s0, s1;
        split2(W1[i], s0, s1);
        g_ws[0][0][n * 256 + k] = s0; g_ws[0][1][n * 256 + k] = s1;
        split2(W2[i], s0, s1);
        g_ws[1][0][n * 256 + k] = s0; g_ws[1][1][n * 256 + k] = s1;
        return;
    }
    __shared__ float Ws[F_IN * D];
    __shared__ float xs[EMB_NODES * F_IN];
    for (int i = t; i < F_IN * D; i += 256) Ws[i] = W[i];
    int n0 = blockIdx.x * EMB_NODES;
    for (int i = t; i < EMB_NODES * F_IN; i += 256) {
        int node = n0 + i / F_IN;
        xs[i] = (node < N_NODES) ? x[(size_t)node * F_IN + (i % F_IN)] : 0.0f;
    }
    __syncthreads();
    float bv = b[t];
    #pragma unroll 1
    for (int j = 0; j < EMB_NODES; j++) {
        int node = n0 + j;
        if (node >= M_PAD) break;
        __nv_bfloat16 s0 = __float2bfloat16(0.0f), s1 = s0;
        if (node < N_NODES) {
            float acc = bv;
            #pragma unroll
            for (int k = 0; k < F_IN; k++) acc += xs[j * F_IN + k] * Ws[k * D + t];
            split2(fmaxf(acc, 0.0f), s0, s1);
        }
        size_t idx = (size_t)node * D + t;
        g_a0[idx] = s0;
        g_a1[idx] = s1;
    }
}

// ---------------- bf16x2 mma.sync GEMM, 2 CTAs/SM, 3-deep A ring ----------------
// B-fragment loads hoisted ABOVE the chunk barrier (B is resident/read-only):
// they overlap the previous chunk's mma tail; only A ldsm remain post-barrier.
// The resident-B cp.async group is retired by a dedicated wait BEFORE the
// mainloop, so hoisted B reads never race the B load (round-14 bug fix).
#define SMEM_A_OFF 65536
#define A_BUFS 3
#define SMEM_GEMM (SMEM_A_OFF + A_BUFS * 16384)   // 114688

__device__ __forceinline__ void load_achunk(uint32_t sb, int t, int m0, int c) {
    int k0 = c * 32;
    uint32_t ab = sb + SMEM_A_OFF + (c % A_BUFS) * 16384;
    #pragma unroll
    for (int j = 0; j < 4; j++) {
        int u = t + 256 * j;                  // 0..1023 16B units
        int row = u >> 3, uu = u & 7;         // uu<4: hi, else lo
        uint32_t dst = ab + row * 128 + ((uu ^ (row & 7)) << 4);
        const __nv_bfloat16* base = (uu < 4) ? g_a0 : g_a1;
        cpa16(dst, base + (size_t)(m0 + row) * D + k0 + (uu & 3) * 8);
    }
    asm volatile("cp.async.commit_group;" ::: "memory");
}

__global__ __launch_bounds__(256, 2) void k_gemm_bf16(const __nv_bfloat16* __restrict__ Wb,
                                                      float* __restrict__ out) {
    extern __shared__ __align__(1024) char smem[];
    const uint32_t sb = smem_u32(smem);
    const int t = threadIdx.x, wid = t >> 5, lane = t & 31;
    const int nq = blockIdx.x & 3;
    const int wm = wid & 3, wn = wid >> 2;
    const int dq = lane >> 3, Lr = lane & 7;

    // load resident B (quarter of W, both splits), one commit group
    #pragma unroll
    for (int j = 0; j < 16; j++) {
        int u = t + 256 * j;                  // 0..4095 16B units
        int s = u >> 11;
        int row = (u & 2047) >> 5;
        int q = u & 31;
        uint32_t dst = sb + s * 32768 + row * 512 + ((q ^ (row & 7)) << 4);
        cpa16(dst, Wb + s * (D * D) + (size_t)(nq * 64 + row) * D + q * 8);
    }
    asm volatile("cp.async.commit_group;" ::: "memory");
    // retire the B group NOW: hoisted B ldsm in the first chunk of the first
    // tile must not race the resident-B load. One-time ~600 cyc cost.
    asm volatile("cp.async.wait_group 0;" ::: "memory");
    __syncthreads();

    // lane geometry
    int rowA[2], xorA[2];
    #pragma unroll
    for (int it = 0; it < 2; it++) {
        rowA[it] = wm * 32 + it * 16 + Lr + (dq & 1) * 8;
        xorA[it] = rowA[it] & 7;
    }
    const int uhiA = dq >> 1;
    int rowB[2], xorB[2];
    #pragma unroll
    for (int g4 = 0; g4 < 2; g4++) {
        rowB[g4] = wn * 32 + g4 * 16 + (dq >> 1) * 8 + Lr;
        xorB[g4] = rowB[g4] & 7;
    }
    const int qloB = dq & 1;

    #pragma unroll 1
    for (int mt = blockIdx.x >> 2; mt < M_TILES; mt += 74) {
        int m0 = mt * 128;
        float C[2][4][4];
        #pragma unroll
        for (int it = 0; it < 2; it++)
            #pragma unroll
            for (int f = 0; f < 4; f++)
                #pragma unroll
                for (int q = 0; q < 4; q++) C[it][f][q] = 0.0f;

        __syncthreads();                      // prev tile fully consumed by all warps
        load_achunk(sb, t, m0, 0);
        load_achunk(sb, t, m0, 1);

        #pragma unroll 1
        for (int c = 0; c < 8; c++) {
            // --- B fragments for the WHOLE chunk, loaded BEFORE the barrier ---
            // (resident smem, retired pre-mainloop; overlaps prev chunk's mmas)
            uint32_t bh[2][4][2], bl[2][4][2];
            #pragma unroll
            for (int kl = 0; kl < 2; kl++) {
                int qb = (c * 2 + kl) * 2 + qloB;
                #pragma unroll
                for (int g4 = 0; g4 < 2; g4++) {
                    uint32_t base = sb + rowB[g4] * 512 + ((qb ^ xorB[g4]) << 4);
                    uint32_t r[4];
                    ldsm4(r, base);
                    bh[kl][2 * g4][0] = r[0]; bh[kl][2 * g4][1] = r[1];
                    bh[kl][2 * g4 + 1][0] = r[2]; bh[kl][2 * g4 + 1][1] = r[3];
                    ldsm4(r, base + 32768);
                    bl[kl][2 * g4][0] = r[0]; bl[kl][2 * g4][1] = r[1];
                    bl[kl][2 * g4 + 1][0] = r[2]; bl[kl][2 * g4 + 1][1] = r[3];
                }
            }

            // A chunk c must have landed (outstanding groups are A-only now)
            if (c < 7) asm volatile("cp.async.wait_group 1;" ::: "memory");
            else       asm volatile("cp.async.wait_group 0;" ::: "memory");
            __syncthreads();
            if (c < 6) load_achunk(sb, t, m0, c + 2);   // into buffer (c-1)%3, just drained

            uint32_t Ab = sb + SMEM_A_OFF + (c % A_BUFS) * 16384;

            #pragma unroll
            for (int kl = 0; kl < 2; kl++) {
                uint32_t ah[2][4], al[2][4];
                #pragma unroll
                for (int it = 0; it < 2; it++) {
                    int uh = kl * 2 + uhiA;
                    uint32_t base = Ab + rowA[it] * 128;
                    ldsm4(ah[it], base + ((uh ^ xorA[it]) << 4));
                    ldsm4(al[it], base + (((uh + 4) ^ xorA[it]) << 4));
                }
                #pragma unroll
                for (int it = 0; it < 2; it++)
                    #pragma unroll
                    for (int f = 0; f < 4; f++)
                        mma16(C[it][f], ah[it], bh[kl][f]);
                #pragma unroll
                for (int it = 0; it < 2; it++)
                    #pragma unroll
                    for (int f = 0; f < 4; f++) {
                        mma16(C[it][f], ah[it], bl[kl][f]);
                        mma16(C[it][f], al[it], bh[kl][f]);
                    }
            }
        }

        // epilogue: direct gmem stores
        #pragma unroll
        for (int it = 0; it < 2; it++) {
            int m = m0 + wm * 32 + it * 16 + (lane >> 2);
            #pragma unroll
            for (int f = 0; f < 4; f++) {
                int col = nq * 64 + wn * 32 + f * 8 + (lane & 3) * 2;
                if (m < N_NODES)
                    *(float2*)(out + (size_t)m * D + col) = make_float2(C[it][f][0], C[it][f][1]);
                if (m + 8 < N_NODES)
                    *(float2*)(out + (size_t)(m + 8) * D + col) = make_float2(C[it][f][2], C[it][f][3]);
            }
        }
    }
}

// ---------------- aggregation: gather over CSR ----------------------------------
// out[i] = bias + dis[i]^2 * hw[i] + sum_{e: dst=i} dis[i]*dis[src] * hw[src]
template<bool RELU, bool TO_SPLITS>
__global__ __launch_bounds__(256) void k_agg(const float* __restrict__ bias,
                                             float* __restrict__ out_ext) {
    int gw = (blockIdx.x * 256 + threadIdx.x) >> 5;
    int lane = threadIdx.x & 31;
    if (gw >= N_NODES) return;
    const float* hw = g_b;
    float dd = g_dis[gw];
    int c0 = lane * 8;
    const float4* hp = (const float4*)(hw + (size_t)gw * D + c0);
    float4 h0 = hp[0], h1 = hp[1];
    float4 bb0 = *(const float4*)(bias + c0);
    float4 bb1 = *(const float4*)(bias + c0 + 4);
    float sw = dd * dd;
    float v[8];
    v[0] = bb0.x + h0.x * sw; v[1] = bb0.y + h0.y * sw;
    v[2] = bb0.z + h0.z * sw; v[3] = bb0.w + h0.w * sw;
    v[4] = bb1.x + h1.x * sw; v[5] = bb1.y + h1.y * sw;
    v[6] = bb1.z + h1.z * sw; v[7] = bb1.w + h1.w * sw;
    int e = g_rowptr[gw], e1 = g_rowptr[gw + 1];
    for (; e + 1 < e1; e += 2) {
        int s0 = g_col[e], s1 = g_col[e + 1];
        float w0 = dd * g_dis[s0], w1 = dd * g_dis[s1];
        const float4* p0 = (const float4*)(hw + (size_t)s0 * D + c0);
        const float4* p1 = (const float4*)(hw + (size_t)s1 * D + c0);
        float4 x0 = p0[0], x1 = p0[1];
        float4 y0 = p1[0], y1 = p1[1];
        v[0] += x0.x * w0 + y0.x * w1; v[1] += x0.y * w0 + y0.y * w1;
        v[2] += x0.z * w0 + y0.z * w1; v[3] += x0.w * w0 + y0.w * w1;
        v[4] += x1.x * w0 + y1.x * w1; v[5] += x1.y * w0 + y1.y * w1;
        v[6] += x1.z * w0 + y1.z * w1; v[7] += x1.w * w0 + y1.w * w1;
    }
    if (e < e1) {
        int s0 = g_col[e];
        float w0 = dd * g_dis[s0];
        const float4* p0 = (const float4*)(hw + (size_t)s0 * D + c0);
        float4 x0 = p0[0], x1 = p0[1];
        v[0] += x0.x * w0; v[1] += x0.y * w0; v[2] += x0.z * w0; v[3] += x0.w * w0;
        v[4] += x1.x * w0; v[5] += x1.y * w0; v[6] += x1.z * w0; v[7] += x1.w * w0;
    }
    if (RELU) {
        #pragma unroll
        for (int i = 0; i < 8; i++) v[i] = fmaxf(v[i], 0.0f);
    }
    if (TO_SPLITS) {
        __align__(16) __nv_bfloat16 s0[8], s1[8];
        #pragma unroll
        for (int i = 0; i < 8; i++) split2(v[i], s0[i], s1[i]);
        size_t idx = (size_t)gw * D + c0;
        *(uint4*)&g_a0[idx] = *(const uint4*)s0;
        *(uint4*)&g_a1[idx] = *(const uint4*)s1;
    } else {
        float4* op = (float4*)(out_ext + (size_t)gw * D + c0);
        op[0] = make_float4(v[0], v[1], v[2], v[3]);
        op[1] = make_float4(v[4], v[5], v[6], v[7]);
    }
}

// ---------------- launch --------------------------------------------------------
extern "C" void kernel_launch(void* const* d_in, const int* in_sizes, int n_in,
                              void* d_out, int out_size) {
    const float* x       = (const float*)d_in[0];
    const int*   ei      = (const int*)d_in[1];
    const float* W_embed = (const float*)d_in[2];
    const float* b_embed = (const float*)d_in[3];
    const float* W1      = (const float*)d_in[4];
    const float* b1      = (const float*)d_in[5];
    const float* W2      = (const float*)d_in[6];
    const float* b2      = (const float*)d_in[7];
    float* out = (float*)d_out;

    cudaFuncSetAttribute(k_gemm_bf16, cudaFuncAttributeMaxDynamicSharedMemorySize, SMEM_GEMM);

    __nv_bfloat16* ws = nullptr;
    float* gb = nullptr;
    cudaGetSymbolAddress((void**)&ws, g_ws);
    cudaGetSymbolAddress((void**)&gb, g_b);

    int agg_blocks = (N_NODES * 32 + 255) / 256;
    int e4_blocks = (N_EDGES / 4 + 255) / 256;

    // fork/join streams: CSR chain overlaps GEMM1 (proven round-13 pattern).
    cudaStream_t side = 0;
    cudaEvent_t ev_fork = nullptr, ev_join = nullptr;
    bool forked =
        (cudaStreamCreateWithFlags(&side, cudaStreamNonBlocking) == cudaSuccess) &&
        (cudaEventCreateWithFlags(&ev_fork, cudaEventDisableTiming) == cudaSuccess) &&
        (cudaEventCreateWithFlags(&ev_join, cudaEventDisableTiming) == cudaSuccess);
    if (!forked) side = 0;

    // main: embed + weight split (merged, launch 1)
    k_embed<<<EMB_BLOCKS + 256, 256>>>(x, W_embed, b_embed, W1, W2);

    if (forked) {
        cudaEventRecord(ev_fork, 0);
        cudaStreamWaitEvent(side, ev_fork, 0);
    }

    // side: CSR chain (concurrent with GEMM1 when forked)
    k_count4<<<e4_blocks, 256, 0, side>>>(ei);

    // main: layer 1 GEMM
    k_gemm_bf16<<<296, 256, SMEM_GEMM>>>(ws, gb);

    k_scan_a<<<SCAN_BLKS, 1024, 0, side>>>();
    k_scan_c<<<SCAN_BLKS, 1024, 0, side>>>();
    k_fill4<<<e4_blocks, 256, 0, side>>>(ei);

    if (forked) {
        cudaEventRecord(ev_join, side);
        cudaStreamWaitEvent(0, ev_join, 0);   // join: agg needs GEMM1 + CSR
    }

    // layer 1 aggregation -> splits for layer 2
    k_agg<true, true><<<agg_blocks, 256>>>(b1, nullptr);

    // layer 2
    k_gemm_bf16<<<296, 256, SMEM_GEMM>>>(ws + 2 * D * D, gb);
    k_agg<false, false><<<agg_blocks, 256>>>(b2, out);
}

// round 17
// speedup vs baseline: 2.0380x; 1.2311x over previous
#include <cuda_runtime.h>
#include <cuda_bf16.h>
#include <cuda_fp16.h>
#include <cstdint>

#define N_NODES 50000
#define N_EDGES 300000
#define D 256
#define F_IN 11
#define M_TILES 391
#define M_PAD (M_TILES * 128)

// ---------------- static scratch ------------------------------------------------
__device__ __align__(16) __nv_bfloat16 g_a0[(size_t)M_PAD * D];  // A hi split
__device__ __align__(16) __nv_bfloat16 g_a1[(size_t)M_PAD * D];  // A lo split
__device__ __align__(16) __half g_b[(size_t)N_NODES * D];        // GEMM output fp16
__device__ __align__(16) __nv_bfloat16 g_ws[2][2][D * D];        // W splits [layer][split][n*256+k]
__device__ float g_dis[N_NODES];
__device__ int   g_cnt[N_NODES];
__device__ int   g_rowptr[N_NODES + 1];
__device__ int   g_cursor[N_NODES];
__device__ int   g_col[N_EDGES];
__device__ int   g_part[64];

// ---------------- helpers -------------------------------------------------------
__device__ __forceinline__ uint32_t smem_u32(const void* p) {
    uint32_t a;
    asm("{ .reg .u64 t; cvta.to.shared.u64 t, %1; cvt.u32.u64 %0, t; }" : "=r"(a) : "l"(p));
    return a;
}
__device__ __forceinline__ void cpa16(uint32_t d, const void* s) {
    asm volatile("cp.async.cg.shared.global [%0], [%1], 16;" :: "r"(d), "l"(s));
}
__device__ __forceinline__ void ldsm4(uint32_t* r, uint32_t a) {
    asm volatile("ldmatrix.sync.aligned.m8n8.x4.shared.b16 {%0,%1,%2,%3}, [%4];"
                 : "=r"(r[0]), "=r"(r[1]), "=r"(r[2]), "=r"(r[3]) : "r"(a));
}
__device__ __forceinline__ void mma16(float* c, const uint32_t* a, const uint32_t* b) {
    asm volatile("mma.sync.aligned.m16n8k16.row.col.f32.bf16.bf16.f32 "
                 "{%0,%1,%2,%3},{%4,%5,%6,%7},{%8,%9},{%0,%1,%2,%3};"
                 : "+f"(c[0]), "+f"(c[1]), "+f"(c[2]), "+f"(c[3])
                 : "r"(a[0]), "r"(a[1]), "r"(a[2]), "r"(a[3]), "r"(b[0]), "r"(b[1]));
}
__device__ __forceinline__ void split2(float x, __nv_bfloat16& s0, __nv_bfloat16& s1) {
    s0 = __float2bfloat16(x);
    s1 = __float2bfloat16(x - __bfloat162float(s0));
}

// ---------------- CSR build -----------------------------------------------------
// g_cnt starts zero (static init on first call; re-zeroed by k_scan_c each call)
__global__ void k_count4(const int* __restrict__ ei) {
    int i = blockIdx.x * 256 + threadIdx.x;
    if (i < N_EDGES / 4) {
        int4 d = ((const int4*)(ei + N_EDGES))[i];
        atomicAdd(&g_cnt[d.x], 1);
        atomicAdd(&g_cnt[d.y], 1);
        atomicAdd(&g_cnt[d.z], 1);
        atomicAdd(&g_cnt[d.w], 1);
    }
}

#define SCAN_BLKS 49
__global__ __launch_bounds__(1024) void k_scan_a() {
    __shared__ int s[1024];
    int t = threadIdx.x, i = blockIdx.x * 1024 + t;
    int v = (i < N_NODES) ? g_cnt[i] : 0;
    s[t] = v;
    __syncthreads();
    #pragma unroll
    for (int off = 1; off < 1024; off <<= 1) {
        int tmp = (t >= off) ? s[t - off] : 0;
        __syncthreads();
        s[t] += tmp;
        __syncthreads();
    }
    if (i < N_NODES) g_rowptr[i] = s[t] - v;   // block-local exclusive
    if (t == 1023) g_part[blockIdx.x] = s[t];
}
__global__ __launch_bounds__(1024) void k_scan_c() {
    __shared__ int soff;
    int t = threadIdx.x, bid = blockIdx.x, i = bid * 1024 + t;
    if (t == 0) {
        int s = 0;
        for (int j = 0; j < bid; j++) s += g_part[j];
        soff = s;
    }
    __syncthreads();
    int off = soff;
    if (i < N_NODES) {
        int r = g_rowptr[i] + off;
        g_rowptr[i] = r;
        g_cursor[i] = r;
        g_dis[i] = rsqrtf((float)(g_cnt[i] + 1));
        g_cnt[i] = 0;                    // restore for next call (graph replay)
    }
    if (i == N_NODES) g_rowptr[N_NODES] = N_EDGES;
}
__global__ void k_fill4(const int* __restrict__ ei) {
    int i = blockIdx.x * 256 + threadIdx.x;
    if (i < N_EDGES / 4) {
        int4 s = ((const int4*)ei)[i];
        int4 d = ((const int4*)(ei + N_EDGES))[i];
        int p;
        p = atomicAdd(&g_cursor[d.x], 1); g_col[p] = s.x;
        p = atomicAdd(&g_cursor[d.y], 1); g_col[p] = s.y;
        p = atomicAdd(&g_cursor[d.z], 1); g_col[p] = s.z;
        p = atomicAdd(&g_cursor[d.w], 1); g_col[p] = s.w;
    }
}

// ---------------- embed + weight-split (merged, branch on blockIdx) -------------
// W column held in registers (11 floats) instead of smem: halves LDS issue.
#define EMB_NODES 8
#define EMB_BLOCKS ((M_PAD + EMB_NODES - 1) / EMB_NODES)
__global__ __launch_bounds__(256) void k_embed(const float* __restrict__ x,
                                               const float* __restrict__ W,
                                               const float* __restrict__ b,
                                               const float* __restrict__ W1,
                                               const float* __restrict__ W2) {
    int t = threadIdx.x;
    if (blockIdx.x >= EMB_BLOCKS) {
        // weight split: one block per 256 elements
        int i = (blockIdx.x - EMB_BLOCKS) * 256 + t;   // i = k*256+n
        int k = i >> 8, n = i & 255;
        __nv_bfloat16 s0, s1;
        split2(W1[i], s0, s1);
        g_ws[0][0][n * 256 + k] = s0; g_ws[0][1][n * 256 + k] = s1;
        split2(W2[i], s0, s1);
        g_ws[1][0][n * 256 + k] = s0; g_ws[1][1][n * 256 + k] = s1;
        return;
    }
    __shared__ float xs[EMB_NODES * F_IN];
    float wr[F_IN];
    #pragma unroll
    for (int k = 0; k < F_IN; k++) wr[k] = W[k * D + t];   // coalesced
    int n0 = blockIdx.x * EMB_NODES;
    for (int i = t; i < EMB_NODES * F_IN; i += 256) {
        int node = n0 + i / F_IN;
        xs[i] = (node < N_NODES) ? x[(size_t)node * F_IN + (i % F_IN)] : 0.0f;
    }
    __syncthreads();
    float bv = b[t];
    #pragma unroll 1
    for (int j = 0; j < EMB_NODES; j++) {
        int node = n0 + j;
        if (node >= M_PAD) break;
        __nv_bfloat16 s0 = __float2bfloat16(0.0f), s1 = s0;
        if (node < N_NODES) {
            float acc = bv;
            #pragma unroll
            for (int k = 0; k < F_IN; k++) acc += xs[j * F_IN + k] * wr[k];
            split2(fmaxf(acc, 0.0f), s0, s1);
        }
        size_t idx = (size_t)node * D + t;
        g_a0[idx] = s0;
        g_a1[idx] = s1;
    }
}

// ---------------- bf16x2 mma.sync GEMM, 2 CTAs/SM, 3-deep A ring ----------------
// Mainloop identical to the proven 237.6us kernel; epilogue stores fp16.
#define SMEM_A_OFF 65536
#define A_BUFS 3
#define SMEM_GEMM (SMEM_A_OFF + A_BUFS * 16384)   // 114688

__device__ __forceinline__ void load_achunk(uint32_t sb, int t, int m0, int c) {
    int k0 = c * 32;
    uint32_t ab = sb + SMEM_A_OFF + (c % A_BUFS) * 16384;
    #pragma unroll
    for (int j = 0; j < 4; j++) {
        int u = t + 256 * j;                  // 0..1023 16B units
        int row = u >> 3, uu = u & 7;         // uu<4: hi, else lo
        uint32_t dst = ab + row * 128 + ((uu ^ (row & 7)) << 4);
        const __nv_bfloat16* base = (uu < 4) ? g_a0 : g_a1;
        cpa16(dst, base + (size_t)(m0 + row) * D + k0 + (uu & 3) * 8);
    }
    asm volatile("cp.async.commit_group;" ::: "memory");
}

__global__ __launch_bounds__(256, 2) void k_gemm_bf16(const __nv_bfloat16* __restrict__ Wb,
                                                      __half* __restrict__ out) {
    extern __shared__ __align__(1024) char smem[];
    const uint32_t sb = smem_u32(smem);
    const int t = threadIdx.x, wid = t >> 5, lane = t & 31;
    const int nq = blockIdx.x & 3;
    const int wm = wid & 3, wn = wid >> 2;
    const int dq = lane >> 3, Lr = lane & 7;

    // load resident B (quarter of W, both splits), one commit group
    #pragma unroll
    for (int j = 0; j < 16; j++) {
        int u = t + 256 * j;                  // 0..4095 16B units
        int s = u >> 11;
        int row = (u & 2047) >> 5;
        int q = u & 31;
        uint32_t dst = sb + s * 32768 + row * 512 + ((q ^ (row & 7)) << 4);
        cpa16(dst, Wb + s * (D * D) + (size_t)(nq * 64 + row) * D + q * 8);
    }
    asm volatile("cp.async.commit_group;" ::: "memory");
    // retire the B group before any B ldsm (proven round-15 ordering)
    asm volatile("cp.async.wait_group 0;" ::: "memory");
    __syncthreads();

    // lane geometry
    int rowA[2], xorA[2];
    #pragma unroll
    for (int it = 0; it < 2; it++) {
        rowA[it] = wm * 32 + it * 16 + Lr + (dq & 1) * 8;
        xorA[it] = rowA[it] & 7;
    }
    const int uhiA = dq >> 1;
    int rowB[2], xorB[2];
    #pragma unroll
    for (int g4 = 0; g4 < 2; g4++) {
        rowB[g4] = wn * 32 + g4 * 16 + (dq >> 1) * 8 + Lr;
        xorB[g4] = rowB[g4] & 7;
    }
    const int qloB = dq & 1;

    #pragma unroll 1
    for (int mt = blockIdx.x >> 2; mt < M_TILES; mt += 74) {
        int m0 = mt * 128;
        float C[2][4][4];
        #pragma unroll
        for (int it = 0; it < 2; it++)
            #pragma unroll
            for (int f = 0; f < 4; f++)
                #pragma unroll
                for (int q = 0; q < 4; q++) C[it][f][q] = 0.0f;

        __syncthreads();                      // prev tile fully consumed by all warps
        load_achunk(sb, t, m0, 0);
        load_achunk(sb, t, m0, 1);

        #pragma unroll 1
        for (int c = 0; c < 8; c++) {
            // B fragments for the chunk (resident smem, retired pre-mainloop)
            uint32_t bh[2][4][2], bl[2][4][2];
            #pragma unroll
            for (int kl = 0; kl < 2; kl++) {
                int qb = (c * 2 + kl) * 2 + qloB;
                #pragma unroll
                for (int g4 = 0; g4 < 2; g4++) {
                    uint32_t base = sb + rowB[g4] * 512 + ((qb ^ xorB[g4]) << 4);
                    uint32_t r[4];
                    ldsm4(r, base);
                    bh[kl][2 * g4][0] = r[0]; bh[kl][2 * g4][1] = r[1];
                    bh[kl][2 * g4 + 1][0] = r[2]; bh[kl][2 * g4 + 1][1] = r[3];
                    ldsm4(r, base + 32768);
                    bl[kl][2 * g4][0] = r[0]; bl[kl][2 * g4][1] = r[1];
                    bl[kl][2 * g4 + 1][0] = r[2]; bl[kl][2 * g4 + 1][1] = r[3];
                }
            }

            if (c < 7) asm volatile("cp.async.wait_group 1;" ::: "memory");
            else       asm volatile("cp.async.wait_group 0;" ::: "memory");
            __syncthreads();
            if (c < 6) load_achunk(sb, t, m0, c + 2);   // into buffer (c-1)%3, just drained

            uint32_t Ab = sb + SMEM_A_OFF + (c % A_BUFS) * 16384;

            #pragma unroll
            for (int kl = 0; kl < 2; kl++) {
                uint32_t ah[2][4], al[2][4];
                #pragma unroll
                for (int it = 0; it < 2; it++) {
                    int uh = kl * 2 + uhiA;
                    uint32_t base = Ab + rowA[it] * 128;
                    ldsm4(ah[it], base + ((uh ^ xorA[it]) << 4));
                    ldsm4(al[it], base + (((uh + 4) ^ xorA[it]) << 4));
                }
                #pragma unroll
                for (int it = 0; it < 2; it++)
                    #pragma unroll
                    for (int f = 0; f < 4; f++)
                        mma16(C[it][f], ah[it], bh[kl][f]);
                #pragma unroll
                for (int it = 0; it < 2; it++)
                    #pragma unroll
                    for (int f = 0; f < 4; f++) {
                        mma16(C[it][f], ah[it], bl[kl][f]);
                        mma16(C[it][f], al[it], bh[kl][f]);
                    }
            }
        }

        // epilogue: fp16 stores (halves C-write + downstream agg read traffic)
        #pragma unroll
        for (int it = 0; it < 2; it++) {
            int m = m0 + wm * 32 + it * 16 + (lane >> 2);
            #pragma unroll
            for (int f = 0; f < 4; f++) {
                int col = nq * 64 + wn * 32 + f * 8 + (lane & 3) * 2;
                if (m < N_NODES)
                    *(__half2*)(out + (size_t)m * D + col) =
                        __floats2half2_rn(C[it][f][0], C[it][f][1]);
                if (m + 8 < N_NODES)
                    *(__half2*)(out + (size_t)(m + 8) * D + col) =
                        __floats2half2_rn(C[it][f][2], C[it][f][3]);
            }
        }
    }
}

// ---------------- aggregation: gather over CSR (fp16 hw) ------------------------
// out[i] = bias + dis[i]^2 * hw[i] + sum_{e: dst=i} dis[i]*dis[src] * hw[src]
template<bool RELU, bool TO_SPLITS>
__global__ __launch_bounds__(256) void k_agg(const float* __restrict__ bias,
                                             float* __restrict__ out_ext) {
    int gw = (blockIdx.x * 256 + threadIdx.x) >> 5;
    int lane = threadIdx.x & 31;
    if (gw >= N_NODES) return;
    const __half* hw = g_b;
    float dd = g_dis[gw];
    int c0 = lane * 8;
    float v[8];
    {
        uint4 hv = *(const uint4*)(hw + (size_t)gw * D + c0);   // 8 fp16 = 16B
        const __half2* hh = (const __half2*)&hv;
        float4 bb0 = *(const float4*)(bias + c0);
        float4 bb1 = *(const float4*)(bias + c0 + 4);
        float sw = dd * dd;
        float2 p0 = __half22float2(hh[0]), p1 = __half22float2(hh[1]);
        float2 p2 = __half22float2(hh[2]), p3 = __half22float2(hh[3]);
        v[0] = bb0.x + p0.x * sw; v[1] = bb0.y + p0.y * sw;
        v[2] = bb0.z + p1.x * sw; v[3] = bb0.w + p1.y * sw;
        v[4] = bb1.x + p2.x * sw; v[5] = bb1.y + p2.y * sw;
        v[6] = bb1.z + p3.x * sw; v[7] = bb1.w + p3.y * sw;
    }
    int e = g_rowptr[gw], e1 = g_rowptr[gw + 1];
    for (; e + 1 < e1; e += 2) {
        int s0 = g_col[e], s1 = g_col[e + 1];
        float w0 = dd * g_dis[s0], w1 = dd * g_dis[s1];
        uint4 a = *(const uint4*)(hw + (size_t)s0 * D + c0);
        uint4 b = *(const uint4*)(hw + (size_t)s1 * D + c0);
        const __half2* ha = (const __half2*)&a;
        const __half2* hb = (const __half2*)&b;
        #pragma unroll
        for (int q = 0; q < 4; q++) {
            float2 pa = __half22float2(ha[q]);
            float2 pb = __half22float2(hb[q]);
            v[2 * q]     += pa.x * w0 + pb.x * w1;
            v[2 * q + 1] += pa.y * w0 + pb.y * w1;
        }
    }
    if (e < e1) {
        int s0 = g_col[e];
        float w0 = dd * g_dis[s0];
        uint4 a = *(const uint4*)(hw + (size_t)s0 * D + c0);
        const __half2* ha = (const __half2*)&a;
        #pragma unroll
        for (int q = 0; q < 4; q++) {
            float2 pa = __half22float2(ha[q]);
            v[2 * q]     += pa.x * w0;
            v[2 * q + 1] += pa.y * w0;
        }
    }
    if (RELU) {
        #pragma unroll
        for (int i = 0; i < 8; i++) v[i] = fmaxf(v[i], 0.0f);
    }
    if (TO_SPLITS) {
        __align__(16) __nv_bfloat16 s0[8], s1[8];
        #pragma unroll
        for (int i = 0; i < 8; i++) split2(v[i], s0[i], s1[i]);
        size_t idx = (size_t)gw * D + c0;
        *(uint4*)&g_a0[idx] = *(const uint4*)s0;
        *(uint4*)&g_a1[idx] = *(const uint4*)s1;
    } else {
        float4* op = (float4*)(out_ext + (size_t)gw * D + c0);
        op[0] = make_float4(v[0], v[1], v[2], v[3]);
        op[1] = make_float4(v[4], v[5], v[6], v[7]);
    }
}

// ---------------- launch --------------------------------------------------------
extern "C" void kernel_launch(void* const* d_in, const int* in_sizes, int n_in,
                              void* d_out, int out_size) {
    const float* x       = (const float*)d_in[0];
    const int*   ei      = (const int*)d_in[1];
    const float* W_embed = (const float*)d_in[2];
    const float* b_embed = (const float*)d_in[3];
    const float* W1      = (const float*)d_in[4];
    const float* b1      = (const float*)d_in[5];
    const float* W2      = (const float*)d_in[6];
    const float* b2      = (const float*)d_in[7];
    float* out = (float*)d_out;

    cudaFuncSetAttribute(k_gemm_bf16, cudaFuncAttributeMaxDynamicSharedMemorySize, SMEM_GEMM);

    __nv_bfloat16* ws = nullptr;
    __half* gb = nullptr;
    cudaGetSymbolAddress((void**)&ws, g_ws);
    cudaGetSymbolAddress((void**)&gb, g_b);

    int agg_blocks = (N_NODES * 32 + 255) / 256;
    int e4_blocks = (N_EDGES / 4 + 255) / 256;

    // fork/join streams: CSR chain overlaps GEMM1 (proven round-13 pattern).
    cudaStream_t side = 0;
    cudaEvent_t ev_fork = nullptr, ev_join = nullptr;
    bool forked =
        (cudaStreamCreateWithFlags(&side, cudaStreamNonBlocking) == cudaSuccess) &&
        (cudaEventCreateWithFlags(&ev_fork, cudaEventDisableTiming) == cudaSuccess) &&
        (cudaEventCreateWithFlags(&ev_join, cudaEventDisableTiming) == cudaSuccess);
    if (!forked) side = 0;

    // main: embed + weight split (merged, launch 1)
    k_embed<<<EMB_BLOCKS + 256, 256>>>(x, W_embed, b_embed, W1, W2);

    if (forked) {
        cudaEventRecord(ev_fork, 0);
        cudaStreamWaitEvent(side, ev_fork, 0);
    }

    // side: CSR chain (concurrent with GEMM1 when forked)
    k_count4<<<e4_blocks, 256, 0, side>>>(ei);

    // main: layer 1 GEMM
    k_gemm_bf16<<<296, 256, SMEM_GEMM>>>(ws, gb);

    k_scan_a<<<SCAN_BLKS, 1024, 0, side>>>();
    k_scan_c<<<SCAN_BLKS, 1024, 0, side>>>();
    k_fill4<<<e4_blocks, 256, 0, side>>>(ei);

    if (forked) {
        cudaEventRecord(ev_join, side);
        cudaStreamWaitEvent(0, ev_join, 0);   // join: agg needs GEMM1 + CSR
    }

    // layer 1 aggregation -> splits for layer 2
    k_agg<true, true><<<agg_blocks, 256>>>(b1, nullptr);

    // layer 2
    k_gemm_bf16<<<296, 256, SMEM_GEMM>>>(ws + 2 * D * D, gb);
    k_agg<false, false><<<agg_blocks, 256>>>(b2, out);
}